// round 10
// baseline (speedup 1.0000x reference)
#include <cuda_runtime.h>
#include <cuda_bf16.h>
#include <math.h>
#include <stdint.h>

// Problem constants
#define S    64
#define NSQ  32
#define NSQC 16
#define LL   2048
#define CC   512
#define EE   128
#define HOUT_ELEMS (S*NSQ*LL)      // 4194304

typedef unsigned long long u64;
typedef unsigned int u32;

// ---------------- scratch (device globals; no allocations allowed) ----------
__device__ float         g_w[S*CC*3];                 // dyn conv weights [s][c][k]
__device__ float         g_b[S*CC];                   // dyn conv bias    [s][c]
__device__ __nv_bfloat16 g_xh[(size_t)S*LL*CC];       // 128 MB  xT hi  [s][l][c]
__device__ __nv_bfloat16 g_xl[(size_t)S*LL*CC];       // 128 MB  xT lo
__device__ __nv_bfloat16 g_w1h[CC*CC];                // W1 hi bf16 [o][c]
__device__ __nv_bfloat16 g_w1l[CC*CC];                // W1 lo bf16
__device__ __nv_bfloat16 g_yh[(size_t)S*LL*CC];       // 128 MB  yT hi  [s][l][c]
__device__ __nv_bfloat16 g_yl[(size_t)S*LL*CC];       // 128 MB  yT lo
__device__ __nv_bfloat16 g_w2h[3*32*CC];              // W2 hi [tap][o][c]
__device__ __nv_bfloat16 g_w2l[3*32*CC];              // W2 lo

// ---------------- mma / ldmatrix / cp.async helpers (sm_80-baseline ISA) ----
__device__ __forceinline__ u32 smem_u32(const void* p) {
    u32 a; asm("{ .reg .u64 t; cvta.to.shared.u64 t, %1; cvt.u32.u64 %0, t; }"
               : "=r"(a) : "l"(p));
    return a;
}
__device__ __forceinline__ void ldm4(u32* r, u32 addr) {
    asm volatile("ldmatrix.sync.aligned.m8n8.x4.shared.b16 {%0,%1,%2,%3}, [%4];"
                 : "=r"(r[0]), "=r"(r[1]), "=r"(r[2]), "=r"(r[3]) : "r"(addr));
}
__device__ __forceinline__ void mma16816(float* d, const u32* a, const u32* b) {
    asm volatile("mma.sync.aligned.m16n8k16.row.col.f32.bf16.bf16.f32 "
                 "{%0,%1,%2,%3}, {%4,%5,%6,%7}, {%8,%9}, {%0,%1,%2,%3};"
                 : "+f"(d[0]), "+f"(d[1]), "+f"(d[2]), "+f"(d[3])
                 : "r"(a[0]), "r"(a[1]), "r"(a[2]), "r"(a[3]), "r"(b[0]), "r"(b[1]));
}
#define CP16(sm, gp)      asm volatile("cp.async.cg.shared.global [%0], [%1], 16;" :: "r"(sm), "l"(gp))
#define CP16Z(sm, gp, sz) asm volatile("cp.async.cg.shared.global [%0], [%1], 16, %2;" :: "r"(sm), "l"(gp), "r"(sz))
#define CP_COMMIT()   asm volatile("cp.async.commit_group;" ::: "memory")
#define CP_WAIT0()    asm volatile("cp.async.wait_group 0;" ::: "memory")
#define CP_WAIT1()    asm volatile("cp.async.wait_group 1;" ::: "memory")

// main-gemm smem tile: 128 rows x 64 bytes, 16B chunks XOR-swizzled
__device__ __forceinline__ u32 soff(int r, int c) {
    return (u32)(r*64 + ((c ^ ((r >> 1) & 3)) * 16));
}
// bf16 hi/lo split packed into one u32 (hi = low half, lo = high half)
__device__ __forceinline__ u32 packhl(float v) {
    __nv_bfloat16 vh = __float2bfloat16_rn(v);
    float rem = v - __bfloat162float(vh);
    __nv_bfloat16 vl = __float2bfloat16_rn(rem);
    return (u32)__bfloat16_as_ushort(vh) | ((u32)__bfloat16_as_ushort(vl) << 16);
}

// ============================================================================
// Kernel A: dynamic weights (emb GEMV) + zero logdet
// ============================================================================
__global__ void dynw_kernel(const float* __restrict__ emb,
                            const float* __restrict__ Wa,
                            const float* __restrict__ ba,
                            const float* __restrict__ Wb,
                            const float* __restrict__ bb,
                            float* __restrict__ logdet)
{
    int s = blockIdx.x;
    __shared__ float e[EE];
    int t = threadIdx.x;
    if (t < EE) e[t] = emb[s*EE + t];
    __syncthreads();

    for (int r = t; r < CC*3 + CC; r += blockDim.x) {
        const float* row; float bias; float* outp;
        if (r < CC*3) { row = Wa + (size_t)r*EE; bias = ba[r]; outp = &g_w[s*CC*3 + r]; }
        else { int r2 = r - CC*3; row = Wb + (size_t)r2*EE; bias = bb[r2]; outp = &g_b[s*CC + r2]; }
        float acc = bias;
        #pragma unroll 8
        for (int k = 0; k < EE; ++k) acc = fmaf(e[k], row[k], acc);
        *outp = acc;
    }
    if (t == 0) logdet[s] = 0.f;
}

// ============================================================================
// Kernel A2: W1 -> bf16 hi/lo split.  grid=512 (o), block=256
// ============================================================================
__global__ void w1cvt_kernel(const float* __restrict__ W1)
{
    int o = blockIdx.x, t = threadIdx.x;
    float2 v = *(const float2*)(W1 + (size_t)o*CC + t*2);
    u32 p0 = packhl(v.x), p1 = packhl(v.y);
    ((u32*)g_w1h)[o*256 + t] = __byte_perm(p0, p1, 0x5410);
    ((u32*)g_w1l)[o*256 + t] = __byte_perm(p0, p1, 0x7632);
}

// ============================================================================
// Kernel A3: W2[o][c][k] -> hi/lo bf16 packed [tap][o][c].  grid=192, 256 thr
// ============================================================================
__global__ void w2cvt_kernel(const float* __restrict__ W2)
{
    int idx = blockIdx.x*256 + threadIdx.x;     // < 3*32*512 = 49152
    int c   = idx & 511;
    int o   = (idx >> 9) & 31;
    int tap = idx >> 14;
    float v = W2[(size_t)o*1536 + c*3 + tap];
    __nv_bfloat16 vh = __float2bfloat16_rn(v);
    float rem = v - __bfloat162float(vh);
    g_w2h[idx] = vh;
    g_w2l[idx] = __float2bfloat16_rn(rem);
}

// ============================================================================
// Kernel B: depthwise conv -> relu -> bf16 hi/lo, TRANSPOSED layout xT[s][l][c]
// grid=(64 ltile, 8 ctile, 64 s), block=256.
// thread = (lq = t>>3, cq = t&7): one l, 8 c's -> one uint4 per array.
// Warp stores 4 contiguous 128B segments (full sectors); short compute batch
// then dense stores keeps MLP high.
// ============================================================================
__global__ __launch_bounds__(256)
void dwconv_kernel(const float* __restrict__ h)
{
    int lt = blockIdx.x, ct = blockIdx.y, s = blockIdx.z;
    int t = threadIdx.x;
    int lq = t >> 3, cq = t & 7;
    int l = lt*32 + lq;

    __shared__ float wsm[64][4];
    {
        int c = t >> 2, j = t & 3;
        int cg = ct*64 + c;
        wsm[c][j] = (j < 3) ? g_w[s*CC*3 + cg*3 + j] : g_b[s*CC + cg];
    }

    // this thread's 8 c's all come from ONE h1 row (cq<4 -> row ct*2, else +1)
    int hrow = ct*2 + (cq >> 2);
    const float* hp = h + ((size_t)s*NSQ + hrow) * LL;
    float a0 = (l > 0)      ? hp[l-1] : 0.f;
    float a1 = hp[l];
    float a2 = (l < LL-1)   ? hp[l+1] : 0.f;
    __syncthreads();

    int cbase = cq*8;
    u32 hh[4], ll2[4];
    #pragma unroll
    for (int q = 0; q < 4; ++q) {
        int i0 = cbase + 2*q;
        float w00 = wsm[i0][0],   w01 = wsm[i0][1],   w02 = wsm[i0][2],   bi0 = wsm[i0][3];
        float w10 = wsm[i0+1][0], w11 = wsm[i0+1][1], w12 = wsm[i0+1][2], bi1 = wsm[i0+1][3];
        float v0 = fmaf(w00, a0, fmaf(w01, a1, fmaf(w02, a2, bi0)));
        float v1 = fmaf(w10, a0, fmaf(w11, a1, fmaf(w12, a2, bi1)));
        u32 p0 = packhl(fmaxf(v0, 0.f));
        u32 p1 = packhl(fmaxf(v1, 0.f));
        hh[q]  = __byte_perm(p0, p1, 0x5410);
        ll2[q] = __byte_perm(p0, p1, 0x7632);
    }

    size_t base = ((size_t)s*LL + l) * CC + ct*64 + cbase;
    *(uint4*)(g_xh + base) = make_uint4(hh[0], hh[1], hh[2], hh[3]);
    *(uint4*)(g_xl + base) = make_uint4(ll2[0], ll2[1], ll2[2], ll2[3]);
}

// ============================================================================
// Kernel C: HMMA GEMM  y = relu(W1 x + b1), bf16 3-term split, fp32 accum.
//   Output written as bf16 hi/lo TRANSPOSED yT[s][l][c] (smem-staged).
//   CTA tile 128x128, K-chunk 32, 3-stage cp.async pipeline
//   grid=(16 bn, 4 bm, 64 s), 256 threads, 2 CTAs/SM
// ============================================================================
#define GT_BYTES 8192
#define GBUF_BYTES 32768
#define GSMEM_TOTAL (3*GBUF_BYTES)       // 98304; epilogue reuses first 67584B

__global__ __launch_bounds__(256, 2)
void gemm_mma_kernel(const float* __restrict__ b1)
{
    extern __shared__ __align__(128) char smem[];
    u32 sb = smem_u32(smem);
    int t = threadIdx.x, lane = t & 31, wid = t >> 5;
    int bn = blockIdx.x, bm = blockIdx.y, s = blockIdx.z;
    int wm = wid & 3;
    int wn = wid >> 2;

    int r_ld[2], c_ld[2];
    #pragma unroll
    for (int i = 0; i < 2; ++i) { int idx = t + i*256; r_ld[i] = idx >> 2; c_ld[i] = idx & 3; }

    const __nv_bfloat16* Ah = g_w1h;
    const __nv_bfloat16* Al = g_w1l;
    const __nv_bfloat16* Bh = g_xh + (size_t)s*LL*CC;
    const __nv_bfloat16* Bl = g_xl + (size_t)s*LL*CC;

    auto load_buf = [&](int buf, int kt) {
        u32 base = sb + buf*GBUF_BYTES;
        int k0 = kt*32;
        #pragma unroll
        for (int i = 0; i < 2; ++i) {
            int r = r_ld[i], c = c_ld[i];
            u32 so = soff(r, c);
            size_t ka = (size_t)(bm*128 + r)*CC + k0 + c*8;
            size_t kb = (size_t)(bn*128 + r)*CC + k0 + c*8;
            CP16(base + 0*GT_BYTES + so, Ah + ka);
            CP16(base + 1*GT_BYTES + so, Al + ka);
            CP16(base + 2*GT_BYTES + so, Bh + kb);
            CP16(base + 3*GT_BYTES + so, Bl + kb);
        }
    };

    float acc[2][8][4];
    #pragma unroll
    for (int i = 0; i < 2; ++i)
        #pragma unroll
        for (int j = 0; j < 8; ++j)
            #pragma unroll
            for (int q = 0; q < 4; ++q) acc[i][j][q] = 0.f;

    load_buf(0, 0); CP_COMMIT();
    load_buf(1, 1); CP_COMMIT();

    int buf = 0;
    for (int kt = 0; kt < 16; ++kt) {
        CP_WAIT1();
        __syncthreads();
        if (kt < 14) {
            int nb = buf + 2; if (nb >= 3) nb -= 3;
            load_buf(nb, kt + 2);
            CP_COMMIT();
        }

        u32 base = sb + buf*GBUF_BYTES;
        #pragma unroll
        for (int ks = 0; ks < 2; ++ks) {
            u32 a_h[2][4], a_l[2][4];
            #pragma unroll
            for (int ti = 0; ti < 2; ++ti) {
                int row = wm*32 + ti*16 + (lane & 15);
                int ch  = ks*2 + (lane >> 4);
                u32 so = soff(row, ch);
                ldm4(a_h[ti], base + 0*GT_BYTES + so);
                ldm4(a_l[ti], base + 1*GT_BYTES + so);
            }
            u32 b_h[8][2], b_l[8][2];
            #pragma unroll
            for (int g = 0; g < 4; ++g) {
                int row = wn*64 + g*16 + (lane & 7) + 8*(lane >> 4);
                int ch  = ks*2 + ((lane >> 3) & 1);
                u32 so = soff(row, ch);
                u32 rh[4], rl[4];
                ldm4(rh, base + 2*GT_BYTES + so);
                ldm4(rl, base + 3*GT_BYTES + so);
                b_h[2*g][0] = rh[0]; b_h[2*g][1] = rh[1];
                b_h[2*g+1][0] = rh[2]; b_h[2*g+1][1] = rh[3];
                b_l[2*g][0] = rl[0]; b_l[2*g][1] = rl[1];
                b_l[2*g+1][0] = rl[2]; b_l[2*g+1][1] = rl[3];
            }
            #pragma unroll
            for (int i = 0; i < 2; ++i)
                #pragma unroll
                for (int j = 0; j < 8; ++j) {
                    mma16816(acc[i][j], a_h[i], b_h[j]);
                    mma16816(acc[i][j], a_h[i], b_l[j]);
                    mma16816(acc[i][j], a_l[i], b_h[j]);
                }
        }
        if (++buf == 3) buf = 0;
    }

    // ---- epilogue: relu(+bias) -> packed (hi|lo<<16) u32, smem transpose ----
    // smem layout: u32 ysm2[l 128][o 128], row stride 132 u32 (bank-skewed)
    __syncthreads();
    u32* ysm2 = (u32*)smem;
    #pragma unroll
    for (int i = 0; i < 2; ++i) {
        int rA = wm*32 + i*16 + (lane >> 2);
        int rB = rA + 8;
        float bA = b1[bm*128 + rA], bB = b1[bm*128 + rB];
        #pragma unroll
        for (int j = 0; j < 8; ++j) {
            int lc = wn*64 + j*8 + 2*(lane & 3);
            float* d = acc[i][j];
            ysm2[lc*132 + rA]       = packhl(fmaxf(d[0] + bA, 0.f));
            ysm2[(lc+1)*132 + rA]   = packhl(fmaxf(d[1] + bA, 0.f));
            ysm2[lc*132 + rB]       = packhl(fmaxf(d[2] + bB, 0.f));
            ysm2[(lc+1)*132 + rB]   = packhl(fmaxf(d[3] + bB, 0.f));
        }
    }
    __syncthreads();
    {
        int lr = t >> 1, half = t & 1;
        size_t gbase = ((size_t)s*LL + bn*128 + lr)*CC + bm*128 + half*64;
        const u32* src = ysm2 + lr*132 + half*64;
        #pragma unroll
        for (int q = 0; q < 8; ++q) {
            uint4 w0 = *(const uint4*)(src + q*8);
            uint4 w1 = *(const uint4*)(src + q*8 + 4);
            uint4 vh = make_uint4(__byte_perm(w0.x, w0.y, 0x5410),
                                  __byte_perm(w0.z, w0.w, 0x5410),
                                  __byte_perm(w1.x, w1.y, 0x5410),
                                  __byte_perm(w1.z, w1.w, 0x5410));
            uint4 vl = make_uint4(__byte_perm(w0.x, w0.y, 0x7632),
                                  __byte_perm(w0.z, w0.w, 0x7632),
                                  __byte_perm(w1.x, w1.y, 0x7632),
                                  __byte_perm(w1.z, w1.w, 0x7632));
            *(uint4*)(g_yh + gbase + q*8) = vh;
            *(uint4*)(g_yl + gbase + q*8) = vl;
        }
    }
}

// ============================================================================
// Kernel D: conv2 via HMMA.  out[o][l] = sum_{c,k} W2[o][c][k] y[c][l+k-1]
//   M=32, N=128 per CTA (2 CTAs/SM), K = 512 c x 3 taps, c-chunks of 32,
//   double-buffered cp.async. 8 warps, warp tile 32m x 16n.
//   Fused sigmoid/coupling/logdet/h1-copy.  grid=(16 ltile, 64 s), 256 thr
// ============================================================================
#define C2_BT   10400          // B tile: 130 rows x 80B
#define C2_AT   7680           // A tile: 96 rows x 80B
#define C2_STAGE (2*C2_BT + 2*C2_AT)       // 36160
#define C2_BB(b) ((b)*C2_STAGE)            // Bh; Bl = +C2_BT
#define C2_AB(b) ((b)*C2_STAGE + 2*C2_BT)  // Ah; Al = +C2_AT
#define C2_SMEM  (2*C2_STAGE)              // 72320

__global__ __launch_bounds__(256, 2)
void conv2_mma_kernel(const float* __restrict__ h,
                      const float* __restrict__ b2,
                      float* __restrict__ out)
{
    extern __shared__ __align__(128) char smem[];
    u32 sb = smem_u32(smem);
    int t = threadIdx.x, lane = t & 31, wid = t >> 5;
    int lt = blockIdx.x, s = blockIdx.y;
    int l0 = lt * 128;

    const __nv_bfloat16* Yh = g_yh + (size_t)s*LL*CC;
    const __nv_bfloat16* Yl = g_yl + (size_t)s*LL*CC;

    auto load_cc = [&](int buf, int cc) {
        u32 bB = sb + C2_BB(buf);
        for (int idx = t; idx < 520; idx += 256) {        // 130 rows x 4 chunks
            int r = idx >> 2, ch = idx & 3;
            int l = l0 - 1 + r;
            bool ok = ((unsigned)l < (unsigned)LL);
            u32 sz = ok ? 16u : 0u;
            size_t goff = (size_t)(ok ? l : 0)*CC + cc*32 + ch*8;
            u32 dst = bB + r*80 + ch*16;
            CP16Z(dst,         Yh + goff, sz);
            CP16Z(dst + C2_BT, Yl + goff, sz);
        }
        u32 bA = sb + C2_AB(buf);
        for (int idx = t; idx < 384; idx += 256) {        // 96 rows x 4 chunks
            int r = idx >> 2, ch = idx & 3;
            size_t goff = (size_t)r*CC + cc*32 + ch*8;
            u32 dst = bA + r*80 + ch*16;
            CP16(dst,         g_w2h + goff);
            CP16(dst + C2_AT, g_w2l + goff);
        }
    };

    float acc[2][2][4];
    #pragma unroll
    for (int i = 0; i < 2; ++i)
        #pragma unroll
        for (int j = 0; j < 2; ++j)
            #pragma unroll
            for (int q = 0; q < 4; ++q) acc[i][j][q] = 0.f;

    load_cc(0, 0); CP_COMMIT();

    int buf = 0;
    for (int cc = 0; cc < 16; ++cc) {
        CP_WAIT0();
        __syncthreads();
        if (cc < 15) { load_cc(buf ^ 1, cc + 1); CP_COMMIT(); }

        u32 bB = sb + C2_BB(buf);
        u32 bA = sb + C2_AB(buf);
        #pragma unroll
        for (int tap = 0; tap < 3; ++tap) {
            #pragma unroll
            for (int ks = 0; ks < 2; ++ks) {
                u32 a_h[2][4], a_l[2][4];
                #pragma unroll
                for (int ti = 0; ti < 2; ++ti) {
                    int row = tap*32 + ti*16 + (lane & 15);
                    int ch  = ks*2 + (lane >> 4);
                    u32 ad = bA + row*80 + ch*16;
                    ldm4(a_h[ti], ad);
                    ldm4(a_l[ti], ad + C2_AT);
                }
                u32 b_h[2][2], b_l[2][2];
                {
                    int row = wid*16 + (lane & 7) + 8*(lane >> 4) + tap;
                    int ch  = ks*2 + ((lane >> 3) & 1);
                    u32 ad = bB + row*80 + ch*16;
                    u32 rh[4], rl[4];
                    ldm4(rh, ad);
                    ldm4(rl, ad + C2_BT);
                    b_h[0][0] = rh[0]; b_h[0][1] = rh[1];
                    b_h[1][0] = rh[2]; b_h[1][1] = rh[3];
                    b_l[0][0] = rl[0]; b_l[0][1] = rl[1];
                    b_l[1][0] = rl[2]; b_l[1][1] = rl[3];
                }
                #pragma unroll
                for (int i = 0; i < 2; ++i)
                    #pragma unroll
                    for (int j = 0; j < 2; ++j) {
                        mma16816(acc[i][j], a_h[i], b_h[j]);
                        mma16816(acc[i][j], a_h[i], b_l[j]);
                        mma16816(acc[i][j], a_l[i], b_h[j]);
                    }
            }
        }
        buf ^= 1;
    }

    // ---- fused epilogue: i=0 frags are s-channels (o 0..15), i=1 are m ----
    int o2a = lane >> 2, o2b = o2a + 8;
    float bsA = b2[o2a],      bsB = b2[o2b];
    float bmA = b2[16 + o2a], bmB = b2[16 + o2b];
    const float* h2A = h + ((size_t)s*NSQ + 16 + o2a)*LL;
    const float* h2B = h + ((size_t)s*NSQ + 16 + o2b)*LL;
    float* oA = out + ((size_t)s*NSQ + 16 + o2a)*LL;
    float* oB = out + ((size_t)s*NSQ + 16 + o2b)*LL;

    float logsum = 0.f;
    #pragma unroll
    for (int j = 0; j < 2; ++j) {
        int l = l0 + wid*16 + j*8 + 2*(lane & 3);
        float2 hA = *(const float2*)(h2A + l);
        float2 hB = *(const float2*)(h2B + l);
        float sg0 = 1.f/(1.f + expf(-(acc[0][j][0] + bsA + 2.f))) + 1e-7f;
        float sg1 = 1.f/(1.f + expf(-(acc[0][j][1] + bsA + 2.f))) + 1e-7f;
        float sg2 = 1.f/(1.f + expf(-(acc[0][j][2] + bsB + 2.f))) + 1e-7f;
        float sg3 = 1.f/(1.f + expf(-(acc[0][j][3] + bsB + 2.f))) + 1e-7f;
        float2 rA = make_float2(sg0*(hA.x + acc[1][j][0] + bmA),
                                sg1*(hA.y + acc[1][j][1] + bmA));
        float2 rB = make_float2(sg2*(hB.x + acc[1][j][2] + bmB),
                                sg3*(hB.y + acc[1][j][3] + bmB));
        *(float2*)(oA + l) = rA;
        *(float2*)(oB + l) = rB;
        logsum += logf(sg0) + logf(sg1) + logf(sg2) + logf(sg3);
    }
    #pragma unroll
    for (int off = 16; off; off >>= 1)
        logsum += __shfl_xor_sync(0xffffffffu, logsum, off);
    if (lane == 0)
        atomicAdd(out + HOUT_ELEMS + s, logsum);

    // h1 passthrough for this l-tile
    for (int idx = t; idx < NSQC*128; idx += 256) {
        int ch = idx >> 7;
        int l  = l0 + (idx & 127);
        size_t off = ((size_t)s*NSQ + ch)*LL + l;
        out[off] = h[off];
    }
}

// ============================================================================
extern "C" void kernel_launch(void* const* d_in, const int* in_sizes, int n_in,
                              void* d_out, int out_size)
{
    const float* h   = (const float*)d_in[0];
    const float* emb = (const float*)d_in[1];
    const float* Wa  = (const float*)d_in[2];
    const float* ba  = (const float*)d_in[3];
    const float* Wb  = (const float*)d_in[4];
    const float* bb  = (const float*)d_in[5];
    const float* W1  = (const float*)d_in[6];
    const float* b1  = (const float*)d_in[7];
    const float* W2  = (const float*)d_in[8];
    const float* b2  = (const float*)d_in[9];
    float* out = (float*)d_out;

    static bool attr_set = false;
    if (!attr_set) {
        cudaFuncSetAttribute(gemm_mma_kernel,
                             cudaFuncAttributeMaxDynamicSharedMemorySize, GSMEM_TOTAL);
        cudaFuncSetAttribute(conv2_mma_kernel,
                             cudaFuncAttributeMaxDynamicSharedMemorySize, C2_SMEM);
        attr_set = true;
    }

    dynw_kernel<<<S, 256>>>(emb, Wa, ba, Wb, bb, out + HOUT_ELEMS);
    w1cvt_kernel<<<CC, 256>>>(W1);
    w2cvt_kernel<<<192, 256>>>(W2);
    dwconv_kernel<<<dim3(64, 8, S), 256>>>(h);
    gemm_mma_kernel<<<dim3(16, 4, S), 256, GSMEM_TOTAL>>>(b1);
    conv2_mma_kernel<<<dim3(16, S), 256, C2_SMEM>>>(h, b2, out);
}

// round 11
// speedup vs baseline: 1.1546x; 1.1546x over previous
#include <cuda_runtime.h>
#include <cuda_bf16.h>
#include <math.h>
#include <stdint.h>

// Problem constants
#define S    64
#define NSQ  32
#define NSQC 16
#define LL   2048
#define CC   512
#define EE   128
#define HOUT_ELEMS (S*NSQ*LL)      // 4194304

typedef unsigned long long u64;
typedef unsigned int u32;

// ---------------- scratch (device globals; no allocations allowed) ----------
__device__ float         g_w[S*CC*3];                 // dyn conv weights [s][c][k]
__device__ float         g_b[S*CC];                   // dyn conv bias    [s][c]
__device__ __nv_bfloat16 g_xh[(size_t)S*LL*CC];       // 128 MB  xT hi  [s][l][c]
__device__ __nv_bfloat16 g_xl[(size_t)S*LL*CC];       // 128 MB  xT lo
__device__ __nv_bfloat16 g_w1h[CC*CC];                // W1 hi bf16 [o][c]
__device__ __nv_bfloat16 g_w1l[CC*CC];                // W1 lo bf16
__device__ __nv_bfloat16 g_yh[(size_t)S*LL*CC];       // 128 MB  yT hi  [s][l][c]
__device__ __nv_bfloat16 g_yl[(size_t)S*LL*CC];       // 128 MB  yT lo
__device__ __nv_bfloat16 g_w2h[3*32*CC];              // W2 hi [tap][o][c]
__device__ __nv_bfloat16 g_w2l[3*32*CC];              // W2 lo

// ---------------- mma / ldmatrix / cp.async helpers (sm_80-baseline ISA) ----
__device__ __forceinline__ u32 smem_u32(const void* p) {
    u32 a; asm("{ .reg .u64 t; cvta.to.shared.u64 t, %1; cvt.u32.u64 %0, t; }"
               : "=r"(a) : "l"(p));
    return a;
}
__device__ __forceinline__ void ldm4(u32* r, u32 addr) {
    asm volatile("ldmatrix.sync.aligned.m8n8.x4.shared.b16 {%0,%1,%2,%3}, [%4];"
                 : "=r"(r[0]), "=r"(r[1]), "=r"(r[2]), "=r"(r[3]) : "r"(addr));
}
__device__ __forceinline__ void mma16816(float* d, const u32* a, const u32* b) {
    asm volatile("mma.sync.aligned.m16n8k16.row.col.f32.bf16.bf16.f32 "
                 "{%0,%1,%2,%3}, {%4,%5,%6,%7}, {%8,%9}, {%0,%1,%2,%3};"
                 : "+f"(d[0]), "+f"(d[1]), "+f"(d[2]), "+f"(d[3])
                 : "r"(a[0]), "r"(a[1]), "r"(a[2]), "r"(a[3]), "r"(b[0]), "r"(b[1]));
}
#define CP16(sm, gp)      asm volatile("cp.async.cg.shared.global [%0], [%1], 16;" :: "r"(sm), "l"(gp))
#define CP16Z(sm, gp, sz) asm volatile("cp.async.cg.shared.global [%0], [%1], 16, %2;" :: "r"(sm), "l"(gp), "r"(sz))
#define CP_COMMIT()   asm volatile("cp.async.commit_group;" ::: "memory")
#define CP_WAIT0()    asm volatile("cp.async.wait_group 0;" ::: "memory")
#define CP_WAIT1()    asm volatile("cp.async.wait_group 1;" ::: "memory")

// main-gemm smem tile: 128 rows x 64 bytes, 16B chunks XOR-swizzled
__device__ __forceinline__ u32 soff(int r, int c) {
    return (u32)(r*64 + ((c ^ ((r >> 1) & 3)) * 16));
}
// bf16 hi/lo split packed into one u32 (hi = low half, lo = high half)
__device__ __forceinline__ u32 packhl(float v) {
    __nv_bfloat16 vh = __float2bfloat16_rn(v);
    float rem = v - __bfloat162float(vh);
    __nv_bfloat16 vl = __float2bfloat16_rn(rem);
    return (u32)__bfloat16_as_ushort(vh) | ((u32)__bfloat16_as_ushort(vl) << 16);
}

// ============================================================================
// Kernel A: dynamic weights (emb GEMV) + zero logdet
// ============================================================================
__global__ void dynw_kernel(const float* __restrict__ emb,
                            const float* __restrict__ Wa,
                            const float* __restrict__ ba,
                            const float* __restrict__ Wb,
                            const float* __restrict__ bb,
                            float* __restrict__ logdet)
{
    int s = blockIdx.x;
    __shared__ float e[EE];
    int t = threadIdx.x;
    if (t < EE) e[t] = emb[s*EE + t];
    __syncthreads();

    for (int r = t; r < CC*3 + CC; r += blockDim.x) {
        const float* row; float bias; float* outp;
        if (r < CC*3) { row = Wa + (size_t)r*EE; bias = ba[r]; outp = &g_w[s*CC*3 + r]; }
        else { int r2 = r - CC*3; row = Wb + (size_t)r2*EE; bias = bb[r2]; outp = &g_b[s*CC + r2]; }
        float acc = bias;
        #pragma unroll 8
        for (int k = 0; k < EE; ++k) acc = fmaf(e[k], row[k], acc);
        *outp = acc;
    }
    if (t == 0) logdet[s] = 0.f;
}

// ============================================================================
// Kernel A2: W1 -> bf16 hi/lo split.  grid=512 (o), block=256
// ============================================================================
__global__ void w1cvt_kernel(const float* __restrict__ W1)
{
    int o = blockIdx.x, t = threadIdx.x;
    float2 v = *(const float2*)(W1 + (size_t)o*CC + t*2);
    u32 p0 = packhl(v.x), p1 = packhl(v.y);
    ((u32*)g_w1h)[o*256 + t] = __byte_perm(p0, p1, 0x5410);
    ((u32*)g_w1l)[o*256 + t] = __byte_perm(p0, p1, 0x7632);
}

// ============================================================================
// Kernel A3: W2[o][c][k] -> hi/lo bf16 packed [tap][o][c].  grid=192, 256 thr
// ============================================================================
__global__ void w2cvt_kernel(const float* __restrict__ W2)
{
    int idx = blockIdx.x*256 + threadIdx.x;     // < 3*32*512 = 49152
    int c   = idx & 511;
    int o   = (idx >> 9) & 31;
    int tap = idx >> 14;
    float v = W2[(size_t)o*1536 + c*3 + tap];
    __nv_bfloat16 vh = __float2bfloat16_rn(v);
    float rem = v - __bfloat162float(vh);
    g_w2h[idx] = vh;
    g_w2l[idx] = __float2bfloat16_rn(rem);
}

// ============================================================================
// Kernel B: depthwise conv -> relu -> bf16 hi/lo, TRANSPOSED layout xT[s][l][c]
// grid=(8 ltile, 8 ctile, 64 s), block=256 (one l per thread, 64 c's)
// (round-8 version: big register block, dense batched stores — measured 95.7us)
// ============================================================================
__global__ __launch_bounds__(256)
void dwconv_kernel(const float* __restrict__ h)
{
    int lt = blockIdx.x, ct = blockIdx.y, s = blockIdx.z;
    int t = threadIdx.x;
    int l = lt*256 + t;

    __shared__ float wsm[64][4];
    {
        int c = t >> 2, j = t & 3;
        int cg = ct*64 + c;
        wsm[c][j] = (j < 3) ? g_w[s*CC*3 + cg*3 + j] : g_b[s*CC + cg];
    }

    int r0 = ct * 2;
    const float* hp0 = h + ((size_t)s*NSQ + r0) * LL;
    const float* hp1 = h + ((size_t)s*NSQ + r0 + 1) * LL;
    float a0 = (l > 0)      ? hp0[l-1] : 0.f;
    float a1 = hp0[l];
    float a2 = (l < LL-1)   ? hp0[l+1] : 0.f;
    float b0 = (l > 0)      ? hp1[l-1] : 0.f;
    float b1v = hp1[l];
    float b2 = (l < LL-1)   ? hp1[l+1] : 0.f;
    __syncthreads();

    u32 hi[32], lo[32];
    #pragma unroll
    for (int p = 0; p < 32; ++p) {
        u32 hh = 0, ll2 = 0;
        #pragma unroll
        for (int q = 0; q < 2; ++q) {
            int i = p*2 + q;
            float w0 = wsm[i][0], w1 = wsm[i][1], w2 = wsm[i][2], bi = wsm[i][3];
            float v;
            if (i < 32) v = fmaf(w0, a0, fmaf(w1, a1, fmaf(w2, a2, bi)));
            else        v = fmaf(w0, b0, fmaf(w1, b1v, fmaf(w2, b2, bi)));
            v = fmaxf(v, 0.f);
            __nv_bfloat16 vh = __float2bfloat16_rn(v);
            float rem = v - __bfloat162float(vh);
            __nv_bfloat16 vl = __float2bfloat16_rn(rem);
            hh  |= ((u32)__bfloat16_as_ushort(vh)) << (q*16);
            ll2 |= ((u32)__bfloat16_as_ushort(vl)) << (q*16);
        }
        hi[p] = hh; lo[p] = ll2;
    }

    size_t base = ((size_t)s*LL + l) * CC + ct*64;
    uint4* dh = (uint4*)(g_xh + base);
    uint4* dl = (uint4*)(g_xl + base);
    #pragma unroll
    for (int j = 0; j < 8; ++j) {
        dh[j] = make_uint4(hi[4*j], hi[4*j+1], hi[4*j+2], hi[4*j+3]);
        dl[j] = make_uint4(lo[4*j], lo[4*j+1], lo[4*j+2], lo[4*j+3]);
    }
}

// ============================================================================
// Kernel C: HMMA GEMM  y = relu(W1 x + b1), bf16 3-term split, fp32 accum.
//   Output written as bf16 hi/lo TRANSPOSED yT[s][l][c] (smem-staged).
//   CTA tile 128x128, K-chunk 32, 3-stage cp.async pipeline
//   grid=(16 bn, 4 bm, 64 s), 256 threads, 2 CTAs/SM
// ============================================================================
#define GT_BYTES 8192
#define GBUF_BYTES 32768
#define GSMEM_TOTAL (3*GBUF_BYTES)       // 98304; epilogue reuses first 67584B

__global__ __launch_bounds__(256, 2)
void gemm_mma_kernel(const float* __restrict__ b1)
{
    extern __shared__ __align__(128) char smem[];
    u32 sb = smem_u32(smem);
    int t = threadIdx.x, lane = t & 31, wid = t >> 5;
    int bn = blockIdx.x, bm = blockIdx.y, s = blockIdx.z;
    int wm = wid & 3;
    int wn = wid >> 2;

    int r_ld[2], c_ld[2];
    #pragma unroll
    for (int i = 0; i < 2; ++i) { int idx = t + i*256; r_ld[i] = idx >> 2; c_ld[i] = idx & 3; }

    const __nv_bfloat16* Ah = g_w1h;
    const __nv_bfloat16* Al = g_w1l;
    const __nv_bfloat16* Bh = g_xh + (size_t)s*LL*CC;
    const __nv_bfloat16* Bl = g_xl + (size_t)s*LL*CC;

    auto load_buf = [&](int buf, int kt) {
        u32 base = sb + buf*GBUF_BYTES;
        int k0 = kt*32;
        #pragma unroll
        for (int i = 0; i < 2; ++i) {
            int r = r_ld[i], c = c_ld[i];
            u32 so = soff(r, c);
            size_t ka = (size_t)(bm*128 + r)*CC + k0 + c*8;
            size_t kb = (size_t)(bn*128 + r)*CC + k0 + c*8;
            CP16(base + 0*GT_BYTES + so, Ah + ka);
            CP16(base + 1*GT_BYTES + so, Al + ka);
            CP16(base + 2*GT_BYTES + so, Bh + kb);
            CP16(base + 3*GT_BYTES + so, Bl + kb);
        }
    };

    float acc[2][8][4];
    #pragma unroll
    for (int i = 0; i < 2; ++i)
        #pragma unroll
        for (int j = 0; j < 8; ++j)
            #pragma unroll
            for (int q = 0; q < 4; ++q) acc[i][j][q] = 0.f;

    load_buf(0, 0); CP_COMMIT();
    load_buf(1, 1); CP_COMMIT();

    int buf = 0;
    for (int kt = 0; kt < 16; ++kt) {
        CP_WAIT1();
        __syncthreads();
        if (kt < 14) {
            int nb = buf + 2; if (nb >= 3) nb -= 3;
            load_buf(nb, kt + 2);
            CP_COMMIT();
        }

        u32 base = sb + buf*GBUF_BYTES;
        #pragma unroll
        for (int ks = 0; ks < 2; ++ks) {
            u32 a_h[2][4], a_l[2][4];
            #pragma unroll
            for (int ti = 0; ti < 2; ++ti) {
                int row = wm*32 + ti*16 + (lane & 15);
                int ch  = ks*2 + (lane >> 4);
                u32 so = soff(row, ch);
                ldm4(a_h[ti], base + 0*GT_BYTES + so);
                ldm4(a_l[ti], base + 1*GT_BYTES + so);
            }
            u32 b_h[8][2], b_l[8][2];
            #pragma unroll
            for (int g = 0; g < 4; ++g) {
                int row = wn*64 + g*16 + (lane & 7) + 8*(lane >> 4);
                int ch  = ks*2 + ((lane >> 3) & 1);
                u32 so = soff(row, ch);
                u32 rh[4], rl[4];
                ldm4(rh, base + 2*GT_BYTES + so);
                ldm4(rl, base + 3*GT_BYTES + so);
                b_h[2*g][0] = rh[0]; b_h[2*g][1] = rh[1];
                b_h[2*g+1][0] = rh[2]; b_h[2*g+1][1] = rh[3];
                b_l[2*g][0] = rl[0]; b_l[2*g][1] = rl[1];
                b_l[2*g+1][0] = rl[2]; b_l[2*g+1][1] = rl[3];
            }
            #pragma unroll
            for (int i = 0; i < 2; ++i)
                #pragma unroll
                for (int j = 0; j < 8; ++j) {
                    mma16816(acc[i][j], a_h[i], b_h[j]);
                    mma16816(acc[i][j], a_h[i], b_l[j]);
                    mma16816(acc[i][j], a_l[i], b_h[j]);
                }
        }
        if (++buf == 3) buf = 0;
    }

    // ---- epilogue: relu(+bias) -> packed (hi|lo<<16) u32, smem transpose ----
    // smem layout: u32 ysm2[l 128][o 128], row stride 132 u32 (bank-skewed)
    __syncthreads();
    u32* ysm2 = (u32*)smem;
    #pragma unroll
    for (int i = 0; i < 2; ++i) {
        int rA = wm*32 + i*16 + (lane >> 2);
        int rB = rA + 8;
        float bA = b1[bm*128 + rA], bB = b1[bm*128 + rB];
        #pragma unroll
        for (int j = 0; j < 8; ++j) {
            int lc = wn*64 + j*8 + 2*(lane & 3);
            float* d = acc[i][j];
            ysm2[lc*132 + rA]       = packhl(fmaxf(d[0] + bA, 0.f));
            ysm2[(lc+1)*132 + rA]   = packhl(fmaxf(d[1] + bA, 0.f));
            ysm2[lc*132 + rB]       = packhl(fmaxf(d[2] + bB, 0.f));
            ysm2[(lc+1)*132 + rB]   = packhl(fmaxf(d[3] + bB, 0.f));
        }
    }
    __syncthreads();
    {
        int lr = t >> 1, half = t & 1;
        size_t gbase = ((size_t)s*LL + bn*128 + lr)*CC + bm*128 + half*64;
        const u32* src = ysm2 + lr*132 + half*64;
        #pragma unroll
        for (int q = 0; q < 8; ++q) {
            uint4 w0 = *(const uint4*)(src + q*8);
            uint4 w1 = *(const uint4*)(src + q*8 + 4);
            uint4 vh = make_uint4(__byte_perm(w0.x, w0.y, 0x5410),
                                  __byte_perm(w0.z, w0.w, 0x5410),
                                  __byte_perm(w1.x, w1.y, 0x5410),
                                  __byte_perm(w1.z, w1.w, 0x5410));
            uint4 vl = make_uint4(__byte_perm(w0.x, w0.y, 0x7632),
                                  __byte_perm(w0.z, w0.w, 0x7632),
                                  __byte_perm(w1.x, w1.y, 0x7632),
                                  __byte_perm(w1.z, w1.w, 0x7632));
            *(uint4*)(g_yh + gbase + q*8) = vh;
            *(uint4*)(g_yl + gbase + q*8) = vl;
        }
    }
}

// ============================================================================
// Kernel D: conv2 via HMMA.  out[o][l] = sum_{c,k} W2[o][c][k] y[c][l+k-1]
//   M=32, N=128 per CTA (2 CTAs/SM), K = 512 c x 3 taps, c-chunks of 32,
//   double-buffered cp.async. 8 warps, warp tile 32m x 16n.
//   Fused sigmoid/coupling/logdet/h1-copy.  grid=(16 ltile, 64 s), 256 thr
// ============================================================================
#define C2_BT   10400          // B tile: 130 rows x 80B
#define C2_AT   7680           // A tile: 96 rows x 80B
#define C2_STAGE (2*C2_BT + 2*C2_AT)       // 36160
#define C2_BB(b) ((b)*C2_STAGE)            // Bh; Bl = +C2_BT
#define C2_AB(b) ((b)*C2_STAGE + 2*C2_BT)  // Ah; Al = +C2_AT
#define C2_SMEM  (2*C2_STAGE)              // 72320

__global__ __launch_bounds__(256, 2)
void conv2_mma_kernel(const float* __restrict__ h,
                      const float* __restrict__ b2,
                      float* __restrict__ out)
{
    extern __shared__ __align__(128) char smem[];
    u32 sb = smem_u32(smem);
    int t = threadIdx.x, lane = t & 31, wid = t >> 5;
    int lt = blockIdx.x, s = blockIdx.y;
    int l0 = lt * 128;

    const __nv_bfloat16* Yh = g_yh + (size_t)s*LL*CC;
    const __nv_bfloat16* Yl = g_yl + (size_t)s*LL*CC;

    auto load_cc = [&](int buf, int cc) {
        u32 bB = sb + C2_BB(buf);
        for (int idx = t; idx < 520; idx += 256) {        // 130 rows x 4 chunks
            int r = idx >> 2, ch = idx & 3;
            int l = l0 - 1 + r;
            bool ok = ((unsigned)l < (unsigned)LL);
            u32 sz = ok ? 16u : 0u;
            size_t goff = (size_t)(ok ? l : 0)*CC + cc*32 + ch*8;
            u32 dst = bB + r*80 + ch*16;
            CP16Z(dst,         Yh + goff, sz);
            CP16Z(dst + C2_BT, Yl + goff, sz);
        }
        u32 bA = sb + C2_AB(buf);
        for (int idx = t; idx < 384; idx += 256) {        // 96 rows x 4 chunks
            int r = idx >> 2, ch = idx & 3;
            size_t goff = (size_t)r*CC + cc*32 + ch*8;
            u32 dst = bA + r*80 + ch*16;
            CP16(dst,         g_w2h + goff);
            CP16(dst + C2_AT, g_w2l + goff);
        }
    };

    float acc[2][2][4];
    #pragma unroll
    for (int i = 0; i < 2; ++i)
        #pragma unroll
        for (int j = 0; j < 2; ++j)
            #pragma unroll
            for (int q = 0; q < 4; ++q) acc[i][j][q] = 0.f;

    load_cc(0, 0); CP_COMMIT();

    int buf = 0;
    for (int cc = 0; cc < 16; ++cc) {
        CP_WAIT0();
        __syncthreads();
        if (cc < 15) { load_cc(buf ^ 1, cc + 1); CP_COMMIT(); }

        u32 bB = sb + C2_BB(buf);
        u32 bA = sb + C2_AB(buf);
        #pragma unroll
        for (int tap = 0; tap < 3; ++tap) {
            #pragma unroll
            for (int ks = 0; ks < 2; ++ks) {
                u32 a_h[2][4], a_l[2][4];
                #pragma unroll
                for (int ti = 0; ti < 2; ++ti) {
                    int row = tap*32 + ti*16 + (lane & 15);
                    int ch  = ks*2 + (lane >> 4);
                    u32 ad = bA + row*80 + ch*16;
                    ldm4(a_h[ti], ad);
                    ldm4(a_l[ti], ad + C2_AT);
                }
                u32 b_h[2][2], b_l[2][2];
                {
                    int row = wid*16 + (lane & 7) + 8*(lane >> 4) + tap;
                    int ch  = ks*2 + ((lane >> 3) & 1);
                    u32 ad = bB + row*80 + ch*16;
                    u32 rh[4], rl[4];
                    ldm4(rh, ad);
                    ldm4(rl, ad + C2_BT);
                    b_h[0][0] = rh[0]; b_h[0][1] = rh[1];
                    b_h[1][0] = rh[2]; b_h[1][1] = rh[3];
                    b_l[0][0] = rl[0]; b_l[0][1] = rl[1];
                    b_l[1][0] = rl[2]; b_l[1][1] = rl[3];
                }
                #pragma unroll
                for (int i = 0; i < 2; ++i)
                    #pragma unroll
                    for (int j = 0; j < 2; ++j) {
                        mma16816(acc[i][j], a_h[i], b_h[j]);
                        mma16816(acc[i][j], a_h[i], b_l[j]);
                        mma16816(acc[i][j], a_l[i], b_h[j]);
                    }
            }
        }
        buf ^= 1;
    }

    // ---- fused epilogue: i=0 frags are s-channels (o 0..15), i=1 are m ----
    int o2a = lane >> 2, o2b = o2a + 8;
    float bsA = b2[o2a],      bsB = b2[o2b];
    float bmA = b2[16 + o2a], bmB = b2[16 + o2b];
    const float* h2A = h + ((size_t)s*NSQ + 16 + o2a)*LL;
    const float* h2B = h + ((size_t)s*NSQ + 16 + o2b)*LL;
    float* oA = out + ((size_t)s*NSQ + 16 + o2a)*LL;
    float* oB = out + ((size_t)s*NSQ + 16 + o2b)*LL;

    float logsum = 0.f;
    #pragma unroll
    for (int j = 0; j < 2; ++j) {
        int l = l0 + wid*16 + j*8 + 2*(lane & 3);
        float2 hA = *(const float2*)(h2A + l);
        float2 hB = *(const float2*)(h2B + l);
        float sg0 = 1.f/(1.f + expf(-(acc[0][j][0] + bsA + 2.f))) + 1e-7f;
        float sg1 = 1.f/(1.f + expf(-(acc[0][j][1] + bsA + 2.f))) + 1e-7f;
        float sg2 = 1.f/(1.f + expf(-(acc[0][j][2] + bsB + 2.f))) + 1e-7f;
        float sg3 = 1.f/(1.f + expf(-(acc[0][j][3] + bsB + 2.f))) + 1e-7f;
        float2 rA = make_float2(sg0*(hA.x + acc[1][j][0] + bmA),
                                sg1*(hA.y + acc[1][j][1] + bmA));
        float2 rB = make_float2(sg2*(hB.x + acc[1][j][2] + bmB),
                                sg3*(hB.y + acc[1][j][3] + bmB));
        *(float2*)(oA + l) = rA;
        *(float2*)(oB + l) = rB;
        logsum += logf(sg0) + logf(sg1) + logf(sg2) + logf(sg3);
    }
    #pragma unroll
    for (int off = 16; off; off >>= 1)
        logsum += __shfl_xor_sync(0xffffffffu, logsum, off);
    if (lane == 0)
        atomicAdd(out + HOUT_ELEMS + s, logsum);

    // h1 passthrough for this l-tile
    for (int idx = t; idx < NSQC*128; idx += 256) {
        int ch = idx >> 7;
        int l  = l0 + (idx & 127);
        size_t off = ((size_t)s*NSQ + ch)*LL + l;
        out[off] = h[off];
    }
}

// ============================================================================
extern "C" void kernel_launch(void* const* d_in, const int* in_sizes, int n_in,
                              void* d_out, int out_size)
{
    const float* h   = (const float*)d_in[0];
    const float* emb = (const float*)d_in[1];
    const float* Wa  = (const float*)d_in[2];
    const float* ba  = (const float*)d_in[3];
    const float* Wb  = (const float*)d_in[4];
    const float* bb  = (const float*)d_in[5];
    const float* W1  = (const float*)d_in[6];
    const float* b1  = (const float*)d_in[7];
    const float* W2  = (const float*)d_in[8];
    const float* b2  = (const float*)d_in[9];
    float* out = (float*)d_out;

    static bool attr_set = false;
    if (!attr_set) {
        cudaFuncSetAttribute(gemm_mma_kernel,
                             cudaFuncAttributeMaxDynamicSharedMemorySize, GSMEM_TOTAL);
        cudaFuncSetAttribute(conv2_mma_kernel,
                             cudaFuncAttributeMaxDynamicSharedMemorySize, C2_SMEM);
        attr_set = true;
    }

    dynw_kernel<<<S, 256>>>(emb, Wa, ba, Wb, bb, out + HOUT_ELEMS);
    w1cvt_kernel<<<CC, 256>>>(W1);
    w2cvt_kernel<<<192, 256>>>(W2);
    dwconv_kernel<<<dim3(8, 8, S), 256>>>(h);
    gemm_mma_kernel<<<dim3(16, 4, S), 256, GSMEM_TOTAL>>>(b1);
    conv2_mma_kernel<<<dim3(16, S), 256, C2_SMEM>>>(h, b2, out);
}

// round 12
// speedup vs baseline: 1.1600x; 1.0047x over previous
#include <cuda_runtime.h>
#include <cuda_bf16.h>
#include <math.h>
#include <stdint.h>

// Problem constants
#define S    64
#define NSQ  32
#define NSQC 16
#define LL   2048
#define CC   512
#define EE   128
#define HOUT_ELEMS (S*NSQ*LL)      // 4194304

typedef unsigned long long u64;
typedef unsigned int u32;

// ---------------- scratch (device globals; no allocations allowed) ----------
__device__ float         g_w[S*CC*3];                 // dyn conv weights [s][c][k]
__device__ float         g_b[S*CC];                   // dyn conv bias    [s][c]
__device__ __nv_bfloat16 g_xh[(size_t)S*LL*CC];       // 128 MB  xT hi  [s][l][c]
__device__ __nv_bfloat16 g_xl[(size_t)S*LL*CC];       // 128 MB  xT lo
__device__ __nv_bfloat16 g_w1h[CC*CC];                // W1 hi bf16 [o][c]
__device__ __nv_bfloat16 g_w1l[CC*CC];                // W1 lo bf16
__device__ __nv_bfloat16 g_yh[(size_t)S*LL*CC];       // 128 MB  yT hi  [s][l][c]
__device__ __nv_bfloat16 g_yl[(size_t)S*LL*CC];       // 128 MB  yT lo
__device__ __nv_bfloat16 g_w2h[3*32*CC];              // W2 hi [tap][o][c]
__device__ __nv_bfloat16 g_w2l[3*32*CC];              // W2 lo

// ---------------- mma / ldmatrix / cp.async helpers (sm_80-baseline ISA) ----
__device__ __forceinline__ u32 smem_u32(const void* p) {
    u32 a; asm("{ .reg .u64 t; cvta.to.shared.u64 t, %1; cvt.u32.u64 %0, t; }"
               : "=r"(a) : "l"(p));
    return a;
}
__device__ __forceinline__ void ldm4(u32* r, u32 addr) {
    asm volatile("ldmatrix.sync.aligned.m8n8.x4.shared.b16 {%0,%1,%2,%3}, [%4];"
                 : "=r"(r[0]), "=r"(r[1]), "=r"(r[2]), "=r"(r[3]) : "r"(addr));
}
__device__ __forceinline__ void mma16816(float* d, const u32* a, const u32* b) {
    asm volatile("mma.sync.aligned.m16n8k16.row.col.f32.bf16.bf16.f32 "
                 "{%0,%1,%2,%3}, {%4,%5,%6,%7}, {%8,%9}, {%0,%1,%2,%3};"
                 : "+f"(d[0]), "+f"(d[1]), "+f"(d[2]), "+f"(d[3])
                 : "r"(a[0]), "r"(a[1]), "r"(a[2]), "r"(a[3]), "r"(b[0]), "r"(b[1]));
}
#define CP16(sm, gp)      asm volatile("cp.async.cg.shared.global [%0], [%1], 16;" :: "r"(sm), "l"(gp))
#define CP16Z(sm, gp, sz) asm volatile("cp.async.cg.shared.global [%0], [%1], 16, %2;" :: "r"(sm), "l"(gp), "r"(sz))
#define CP_COMMIT()   asm volatile("cp.async.commit_group;" ::: "memory")
#define CP_WAIT0()    asm volatile("cp.async.wait_group 0;" ::: "memory")
#define CP_WAIT1()    asm volatile("cp.async.wait_group 1;" ::: "memory")

// main-gemm smem tile: 128 rows x 64 bytes, 16B chunks XOR-swizzled
__device__ __forceinline__ u32 soff(int r, int c) {
    return (u32)(r*64 + ((c ^ ((r >> 1) & 3)) * 16));
}
// bf16 hi/lo split packed into one u32 (hi = low half, lo = high half)
__device__ __forceinline__ u32 packhl(float v) {
    __nv_bfloat16 vh = __float2bfloat16_rn(v);
    float rem = v - __bfloat162float(vh);
    __nv_bfloat16 vl = __float2bfloat16_rn(rem);
    return (u32)__bfloat16_as_ushort(vh) | ((u32)__bfloat16_as_ushort(vl) << 16);
}

// ============================================================================
// Kernel A: dynamic weights (emb GEMV) + zero logdet.  grid = 32 (half batch)
// ============================================================================
__global__ void dynw_kernel(const float* __restrict__ emb,
                            const float* __restrict__ Wa,
                            const float* __restrict__ ba,
                            const float* __restrict__ Wb,
                            const float* __restrict__ bb,
                            float* __restrict__ logdet, int sofs)
{
    int s = blockIdx.x + sofs;
    __shared__ float e[EE];
    int t = threadIdx.x;
    if (t < EE) e[t] = emb[s*EE + t];
    __syncthreads();

    for (int r = t; r < CC*3 + CC; r += blockDim.x) {
        const float* row; float bias; float* outp;
        if (r < CC*3) { row = Wa + (size_t)r*EE; bias = ba[r]; outp = &g_w[s*CC*3 + r]; }
        else { int r2 = r - CC*3; row = Wb + (size_t)r2*EE; bias = bb[r2]; outp = &g_b[s*CC + r2]; }
        float acc = bias;
        #pragma unroll 8
        for (int k = 0; k < EE; ++k) acc = fmaf(e[k], row[k], acc);
        *outp = acc;
    }
    if (t == 0) logdet[s] = 0.f;
}

// ============================================================================
// Kernel A2: W1 -> bf16 hi/lo split.  grid=512 (o), block=256
// ============================================================================
__global__ void w1cvt_kernel(const float* __restrict__ W1)
{
    int o = blockIdx.x, t = threadIdx.x;
    float2 v = *(const float2*)(W1 + (size_t)o*CC + t*2);
    u32 p0 = packhl(v.x), p1 = packhl(v.y);
    ((u32*)g_w1h)[o*256 + t] = __byte_perm(p0, p1, 0x5410);
    ((u32*)g_w1l)[o*256 + t] = __byte_perm(p0, p1, 0x7632);
}

// ============================================================================
// Kernel A3: W2[o][c][k] -> hi/lo bf16 packed [tap][o][c].  grid=192, 256 thr
// ============================================================================
__global__ void w2cvt_kernel(const float* __restrict__ W2)
{
    int idx = blockIdx.x*256 + threadIdx.x;     // < 3*32*512 = 49152
    int c   = idx & 511;
    int o   = (idx >> 9) & 31;
    int tap = idx >> 14;
    float v = W2[(size_t)o*1536 + c*3 + tap];
    __nv_bfloat16 vh = __float2bfloat16_rn(v);
    float rem = v - __bfloat162float(vh);
    g_w2h[idx] = vh;
    g_w2l[idx] = __float2bfloat16_rn(rem);
}

// ============================================================================
// Kernel B: depthwise conv -> relu -> bf16 hi/lo, TRANSPOSED layout xT[s][l][c]
// grid=(8 ltile, 8 ctile, 32 s-half), block=256 (one l per thread, 64 c's)
// ============================================================================
__global__ __launch_bounds__(256)
void dwconv_kernel(const float* __restrict__ h, int sofs)
{
    int lt = blockIdx.x, ct = blockIdx.y, s = blockIdx.z + sofs;
    int t = threadIdx.x;
    int l = lt*256 + t;

    __shared__ float wsm[64][4];
    {
        int c = t >> 2, j = t & 3;
        int cg = ct*64 + c;
        wsm[c][j] = (j < 3) ? g_w[s*CC*3 + cg*3 + j] : g_b[s*CC + cg];
    }

    int r0 = ct * 2;
    const float* hp0 = h + ((size_t)s*NSQ + r0) * LL;
    const float* hp1 = h + ((size_t)s*NSQ + r0 + 1) * LL;
    float a0 = (l > 0)      ? hp0[l-1] : 0.f;
    float a1 = hp0[l];
    float a2 = (l < LL-1)   ? hp0[l+1] : 0.f;
    float b0 = (l > 0)      ? hp1[l-1] : 0.f;
    float b1v = hp1[l];
    float b2 = (l < LL-1)   ? hp1[l+1] : 0.f;
    __syncthreads();

    u32 hi[32], lo[32];
    #pragma unroll
    for (int p = 0; p < 32; ++p) {
        u32 hh = 0, ll2 = 0;
        #pragma unroll
        for (int q = 0; q < 2; ++q) {
            int i = p*2 + q;
            float w0 = wsm[i][0], w1 = wsm[i][1], w2 = wsm[i][2], bi = wsm[i][3];
            float v;
            if (i < 32) v = fmaf(w0, a0, fmaf(w1, a1, fmaf(w2, a2, bi)));
            else        v = fmaf(w0, b0, fmaf(w1, b1v, fmaf(w2, b2, bi)));
            v = fmaxf(v, 0.f);
            __nv_bfloat16 vh = __float2bfloat16_rn(v);
            float rem = v - __bfloat162float(vh);
            __nv_bfloat16 vl = __float2bfloat16_rn(rem);
            hh  |= ((u32)__bfloat16_as_ushort(vh)) << (q*16);
            ll2 |= ((u32)__bfloat16_as_ushort(vl)) << (q*16);
        }
        hi[p] = hh; lo[p] = ll2;
    }

    size_t base = ((size_t)s*LL + l) * CC + ct*64;
    uint4* dh = (uint4*)(g_xh + base);
    uint4* dl = (uint4*)(g_xl + base);
    #pragma unroll
    for (int j = 0; j < 8; ++j) {
        dh[j] = make_uint4(hi[4*j], hi[4*j+1], hi[4*j+2], hi[4*j+3]);
        dl[j] = make_uint4(lo[4*j], lo[4*j+1], lo[4*j+2], lo[4*j+3]);
    }
}

// ============================================================================
// Kernel C: HMMA GEMM  y = relu(W1 x + b1), bf16 3-term split, fp32 accum.
//   Output written as bf16 hi/lo TRANSPOSED yT[s][l][c] (smem-staged).
//   CTA tile 128x128, K-chunk 32, 3-stage cp.async pipeline
//   grid=(16 bn, 4 bm, 32 s-half), 256 threads, 2 CTAs/SM
// ============================================================================
#define GT_BYTES 8192
#define GBUF_BYTES 32768
#define GSMEM_TOTAL (3*GBUF_BYTES)       // 98304; epilogue reuses first 67584B

__global__ __launch_bounds__(256, 2)
void gemm_mma_kernel(const float* __restrict__ b1, int sofs)
{
    extern __shared__ __align__(128) char smem[];
    u32 sb = smem_u32(smem);
    int t = threadIdx.x, lane = t & 31, wid = t >> 5;
    int bn = blockIdx.x, bm = blockIdx.y, s = blockIdx.z + sofs;
    int wm = wid & 3;
    int wn = wid >> 2;

    int r_ld[2], c_ld[2];
    #pragma unroll
    for (int i = 0; i < 2; ++i) { int idx = t + i*256; r_ld[i] = idx >> 2; c_ld[i] = idx & 3; }

    const __nv_bfloat16* Ah = g_w1h;
    const __nv_bfloat16* Al = g_w1l;
    const __nv_bfloat16* Bh = g_xh + (size_t)s*LL*CC;
    const __nv_bfloat16* Bl = g_xl + (size_t)s*LL*CC;

    auto load_buf = [&](int buf, int kt) {
        u32 base = sb + buf*GBUF_BYTES;
        int k0 = kt*32;
        #pragma unroll
        for (int i = 0; i < 2; ++i) {
            int r = r_ld[i], c = c_ld[i];
            u32 so = soff(r, c);
            size_t ka = (size_t)(bm*128 + r)*CC + k0 + c*8;
            size_t kb = (size_t)(bn*128 + r)*CC + k0 + c*8;
            CP16(base + 0*GT_BYTES + so, Ah + ka);
            CP16(base + 1*GT_BYTES + so, Al + ka);
            CP16(base + 2*GT_BYTES + so, Bh + kb);
            CP16(base + 3*GT_BYTES + so, Bl + kb);
        }
    };

    float acc[2][8][4];
    #pragma unroll
    for (int i = 0; i < 2; ++i)
        #pragma unroll
        for (int j = 0; j < 8; ++j)
            #pragma unroll
            for (int q = 0; q < 4; ++q) acc[i][j][q] = 0.f;

    load_buf(0, 0); CP_COMMIT();
    load_buf(1, 1); CP_COMMIT();

    int buf = 0;
    for (int kt = 0; kt < 16; ++kt) {
        CP_WAIT1();
        __syncthreads();
        if (kt < 14) {
            int nb = buf + 2; if (nb >= 3) nb -= 3;
            load_buf(nb, kt + 2);
            CP_COMMIT();
        }

        u32 base = sb + buf*GBUF_BYTES;
        #pragma unroll
        for (int ks = 0; ks < 2; ++ks) {
            u32 a_h[2][4], a_l[2][4];
            #pragma unroll
            for (int ti = 0; ti < 2; ++ti) {
                int row = wm*32 + ti*16 + (lane & 15);
                int ch  = ks*2 + (lane >> 4);
                u32 so = soff(row, ch);
                ldm4(a_h[ti], base + 0*GT_BYTES + so);
                ldm4(a_l[ti], base + 1*GT_BYTES + so);
            }
            u32 b_h[8][2], b_l[8][2];
            #pragma unroll
            for (int g = 0; g < 4; ++g) {
                int row = wn*64 + g*16 + (lane & 7) + 8*(lane >> 4);
                int ch  = ks*2 + ((lane >> 3) & 1);
                u32 so = soff(row, ch);
                u32 rh[4], rl[4];
                ldm4(rh, base + 2*GT_BYTES + so);
                ldm4(rl, base + 3*GT_BYTES + so);
                b_h[2*g][0] = rh[0]; b_h[2*g][1] = rh[1];
                b_h[2*g+1][0] = rh[2]; b_h[2*g+1][1] = rh[3];
                b_l[2*g][0] = rl[0]; b_l[2*g][1] = rl[1];
                b_l[2*g+1][0] = rl[2]; b_l[2*g+1][1] = rl[3];
            }
            #pragma unroll
            for (int i = 0; i < 2; ++i)
                #pragma unroll
                for (int j = 0; j < 8; ++j) {
                    mma16816(acc[i][j], a_h[i], b_h[j]);
                    mma16816(acc[i][j], a_h[i], b_l[j]);
                    mma16816(acc[i][j], a_l[i], b_h[j]);
                }
        }
        if (++buf == 3) buf = 0;
    }

    // ---- epilogue: relu(+bias) -> packed (hi|lo<<16) u32, smem transpose ----
    // smem layout: u32 ysm2[l 128][o 128], row stride 132 u32 (bank-skewed)
    __syncthreads();
    u32* ysm2 = (u32*)smem;
    #pragma unroll
    for (int i = 0; i < 2; ++i) {
        int rA = wm*32 + i*16 + (lane >> 2);
        int rB = rA + 8;
        float bA = b1[bm*128 + rA], bB = b1[bm*128 + rB];
        #pragma unroll
        for (int j = 0; j < 8; ++j) {
            int lc = wn*64 + j*8 + 2*(lane & 3);
            float* d = acc[i][j];
            ysm2[lc*132 + rA]       = packhl(fmaxf(d[0] + bA, 0.f));
            ysm2[(lc+1)*132 + rA]   = packhl(fmaxf(d[1] + bA, 0.f));
            ysm2[lc*132 + rB]       = packhl(fmaxf(d[2] + bB, 0.f));
            ysm2[(lc+1)*132 + rB]   = packhl(fmaxf(d[3] + bB, 0.f));
        }
    }
    __syncthreads();
    {
        int lr = t >> 1, half = t & 1;
        size_t gbase = ((size_t)s*LL + bn*128 + lr)*CC + bm*128 + half*64;
        const u32* src = ysm2 + lr*132 + half*64;
        #pragma unroll
        for (int q = 0; q < 8; ++q) {
            uint4 w0 = *(const uint4*)(src + q*8);
            uint4 w1 = *(const uint4*)(src + q*8 + 4);
            uint4 vh = make_uint4(__byte_perm(w0.x, w0.y, 0x5410),
                                  __byte_perm(w0.z, w0.w, 0x5410),
                                  __byte_perm(w1.x, w1.y, 0x5410),
                                  __byte_perm(w1.z, w1.w, 0x5410));
            uint4 vl = make_uint4(__byte_perm(w0.x, w0.y, 0x7632),
                                  __byte_perm(w0.z, w0.w, 0x7632),
                                  __byte_perm(w1.x, w1.y, 0x7632),
                                  __byte_perm(w1.z, w1.w, 0x7632));
            *(uint4*)(g_yh + gbase + q*8) = vh;
            *(uint4*)(g_yl + gbase + q*8) = vl;
        }
    }
}

// ============================================================================
// Kernel D: conv2 via HMMA.  out[o][l] = sum_{c,k} W2[o][c][k] y[c][l+k-1]
//   M=32, N=128 per CTA (2 CTAs/SM), K = 512 c x 3 taps, c-chunks of 32,
//   double-buffered cp.async. 8 warps, warp tile 32m x 16n.
//   Fused sigmoid/coupling/logdet/h1-copy.  grid=(16 ltile, 32 s-half)
// ============================================================================
#define C2_BT   10400          // B tile: 130 rows x 80B
#define C2_AT   7680           // A tile: 96 rows x 80B
#define C2_STAGE (2*C2_BT + 2*C2_AT)       // 36160
#define C2_BB(b) ((b)*C2_STAGE)            // Bh; Bl = +C2_BT
#define C2_AB(b) ((b)*C2_STAGE + 2*C2_BT)  // Ah; Al = +C2_AT
#define C2_SMEM  (2*C2_STAGE)              // 72320

__global__ __launch_bounds__(256, 2)
void conv2_mma_kernel(const float* __restrict__ h,
                      const float* __restrict__ b2,
                      float* __restrict__ out, int sofs)
{
    extern __shared__ __align__(128) char smem[];
    u32 sb = smem_u32(smem);
    int t = threadIdx.x, lane = t & 31, wid = t >> 5;
    int lt = blockIdx.x, s = blockIdx.y + sofs;
    int l0 = lt * 128;

    const __nv_bfloat16* Yh = g_yh + (size_t)s*LL*CC;
    const __nv_bfloat16* Yl = g_yl + (size_t)s*LL*CC;

    auto load_cc = [&](int buf, int cc) {
        u32 bB = sb + C2_BB(buf);
        for (int idx = t; idx < 520; idx += 256) {        // 130 rows x 4 chunks
            int r = idx >> 2, ch = idx & 3;
            int l = l0 - 1 + r;
            bool ok = ((unsigned)l < (unsigned)LL);
            u32 sz = ok ? 16u : 0u;
            size_t goff = (size_t)(ok ? l : 0)*CC + cc*32 + ch*8;
            u32 dst = bB + r*80 + ch*16;
            CP16Z(dst,         Yh + goff, sz);
            CP16Z(dst + C2_BT, Yl + goff, sz);
        }
        u32 bA = sb + C2_AB(buf);
        for (int idx = t; idx < 384; idx += 256) {        // 96 rows x 4 chunks
            int r = idx >> 2, ch = idx & 3;
            size_t goff = (size_t)r*CC + cc*32 + ch*8;
            u32 dst = bA + r*80 + ch*16;
            CP16(dst,         g_w2h + goff);
            CP16(dst + C2_AT, g_w2l + goff);
        }
    };

    float acc[2][2][4];
    #pragma unroll
    for (int i = 0; i < 2; ++i)
        #pragma unroll
        for (int j = 0; j < 2; ++j)
            #pragma unroll
            for (int q = 0; q < 4; ++q) acc[i][j][q] = 0.f;

    load_cc(0, 0); CP_COMMIT();

    int buf = 0;
    for (int cc = 0; cc < 16; ++cc) {
        CP_WAIT0();
        __syncthreads();
        if (cc < 15) { load_cc(buf ^ 1, cc + 1); CP_COMMIT(); }

        u32 bB = sb + C2_BB(buf);
        u32 bA = sb + C2_AB(buf);
        #pragma unroll
        for (int tap = 0; tap < 3; ++tap) {
            #pragma unroll
            for (int ks = 0; ks < 2; ++ks) {
                u32 a_h[2][4], a_l[2][4];
                #pragma unroll
                for (int ti = 0; ti < 2; ++ti) {
                    int row = tap*32 + ti*16 + (lane & 15);
                    int ch  = ks*2 + (lane >> 4);
                    u32 ad = bA + row*80 + ch*16;
                    ldm4(a_h[ti], ad);
                    ldm4(a_l[ti], ad + C2_AT);
                }
                u32 b_h[2][2], b_l[2][2];
                {
                    int row = wid*16 + (lane & 7) + 8*(lane >> 4) + tap;
                    int ch  = ks*2 + ((lane >> 3) & 1);
                    u32 ad = bB + row*80 + ch*16;
                    u32 rh[4], rl[4];
                    ldm4(rh, ad);
                    ldm4(rl, ad + C2_BT);
                    b_h[0][0] = rh[0]; b_h[0][1] = rh[1];
                    b_h[1][0] = rh[2]; b_h[1][1] = rh[3];
                    b_l[0][0] = rl[0]; b_l[0][1] = rl[1];
                    b_l[1][0] = rl[2]; b_l[1][1] = rl[3];
                }
                #pragma unroll
                for (int i = 0; i < 2; ++i)
                    #pragma unroll
                    for (int j = 0; j < 2; ++j) {
                        mma16816(acc[i][j], a_h[i], b_h[j]);
                        mma16816(acc[i][j], a_h[i], b_l[j]);
                        mma16816(acc[i][j], a_l[i], b_h[j]);
                    }
            }
        }
        buf ^= 1;
    }

    // ---- fused epilogue: i=0 frags are s-channels (o 0..15), i=1 are m ----
    int o2a = lane >> 2, o2b = o2a + 8;
    float bsA = b2[o2a],      bsB = b2[o2b];
    float bmA = b2[16 + o2a], bmB = b2[16 + o2b];
    const float* h2A = h + ((size_t)s*NSQ + 16 + o2a)*LL;
    const float* h2B = h + ((size_t)s*NSQ + 16 + o2b)*LL;
    float* oA = out + ((size_t)s*NSQ + 16 + o2a)*LL;
    float* oB = out + ((size_t)s*NSQ + 16 + o2b)*LL;

    float logsum = 0.f;
    #pragma unroll
    for (int j = 0; j < 2; ++j) {
        int l = l0 + wid*16 + j*8 + 2*(lane & 3);
        float2 hA = *(const float2*)(h2A + l);
        float2 hB = *(const float2*)(h2B + l);
        float sg0 = 1.f/(1.f + expf(-(acc[0][j][0] + bsA + 2.f))) + 1e-7f;
        float sg1 = 1.f/(1.f + expf(-(acc[0][j][1] + bsA + 2.f))) + 1e-7f;
        float sg2 = 1.f/(1.f + expf(-(acc[0][j][2] + bsB + 2.f))) + 1e-7f;
        float sg3 = 1.f/(1.f + expf(-(acc[0][j][3] + bsB + 2.f))) + 1e-7f;
        float2 rA = make_float2(sg0*(hA.x + acc[1][j][0] + bmA),
                                sg1*(hA.y + acc[1][j][1] + bmA));
        float2 rB = make_float2(sg2*(hB.x + acc[1][j][2] + bmB),
                                sg3*(hB.y + acc[1][j][3] + bmB));
        *(float2*)(oA + l) = rA;
        *(float2*)(oB + l) = rB;
        logsum += logf(sg0) + logf(sg1) + logf(sg2) + logf(sg3);
    }
    #pragma unroll
    for (int off = 16; off; off >>= 1)
        logsum += __shfl_xor_sync(0xffffffffu, logsum, off);
    if (lane == 0)
        atomicAdd(out + HOUT_ELEMS + s, logsum);

    // h1 passthrough for this l-tile
    for (int idx = t; idx < NSQC*128; idx += 256) {
        int ch = idx >> 7;
        int l  = l0 + (idx & 127);
        size_t off = ((size_t)s*NSQ + ch)*LL + l;
        out[off] = h[off];
    }
}

// ============================================================================
// Launch: two-stream software pipeline over sample halves.
//   stream0: dynwA, dwA, [waits evW] gemmA, conv2A, [waits evJoin]
//   sB:      [waits evFork] w1cvt, w2cvt, dynwB, (evW), [waits evDWA] dwB,
//            gemmB, conv2B, (evJoin)
//   dwB is serialized after dwA so it overlaps gemmA (mem-bound || tensor).
// ============================================================================
extern "C" void kernel_launch(void* const* d_in, const int* in_sizes, int n_in,
                              void* d_out, int out_size)
{
    const float* h   = (const float*)d_in[0];
    const float* emb = (const float*)d_in[1];
    const float* Wa  = (const float*)d_in[2];
    const float* ba  = (const float*)d_in[3];
    const float* Wb  = (const float*)d_in[4];
    const float* bb  = (const float*)d_in[5];
    const float* W1  = (const float*)d_in[6];
    const float* b1  = (const float*)d_in[7];
    const float* W2  = (const float*)d_in[8];
    const float* b2  = (const float*)d_in[9];
    float* out = (float*)d_out;

    static bool init_done = false;
    static cudaStream_t sB;
    static cudaEvent_t evFork, evW, evDWA, evJoin;
    if (!init_done) {
        cudaFuncSetAttribute(gemm_mma_kernel,
                             cudaFuncAttributeMaxDynamicSharedMemorySize, GSMEM_TOTAL);
        cudaFuncSetAttribute(conv2_mma_kernel,
                             cudaFuncAttributeMaxDynamicSharedMemorySize, C2_SMEM);
        cudaStreamCreateWithFlags(&sB, cudaStreamNonBlocking);
        cudaEventCreateWithFlags(&evFork, cudaEventDisableTiming);
        cudaEventCreateWithFlags(&evW,    cudaEventDisableTiming);
        cudaEventCreateWithFlags(&evDWA,  cudaEventDisableTiming);
        cudaEventCreateWithFlags(&evJoin, cudaEventDisableTiming);
        init_done = true;
    }

    const int H = S/2;   // 32 samples per half

    // fork
    cudaEventRecord(evFork, 0);
    cudaStreamWaitEvent(sB, evFork, 0);

    // stream 0: half A
    dynw_kernel<<<H, 256>>>(emb, Wa, ba, Wb, bb, out + HOUT_ELEMS, 0);
    dwconv_kernel<<<dim3(8, 8, H), 256>>>(h, 0);
    cudaEventRecord(evDWA, 0);

    // stream B: weight conversions + half B dyn weights
    w1cvt_kernel<<<CC, 256, 0, sB>>>(W1);
    w2cvt_kernel<<<192, 256, 0, sB>>>(W2);
    cudaEventRecord(evW, sB);
    dynw_kernel<<<H, 256, 0, sB>>>(emb, Wa, ba, Wb, bb, out + HOUT_ELEMS, H);

    // stream 0 half-A compute (needs W1/W2 conversions from sB)
    cudaStreamWaitEvent(0, evW, 0);
    gemm_mma_kernel<<<dim3(16, 4, H), 256, GSMEM_TOTAL>>>(b1, 0);
    conv2_mma_kernel<<<dim3(16, H), 256, C2_SMEM>>>(h, b2, out, 0);

    // stream B half-B chain: dwB AFTER dwA (overlaps gemmA), then gemmB/conv2B
    cudaStreamWaitEvent(sB, evDWA, 0);
    dwconv_kernel<<<dim3(8, 8, H), 256, 0, sB>>>(h, H);
    gemm_mma_kernel<<<dim3(16, 4, H), 256, GSMEM_TOTAL, sB>>>(b1, H);
    conv2_mma_kernel<<<dim3(16, H), 256, C2_SMEM, sB>>>(h, b2, out, H);
    cudaEventRecord(evJoin, sB);

    // join
    cudaStreamWaitEvent(0, evJoin, 0);
}

// round 14
// speedup vs baseline: 1.1645x; 1.0038x over previous
#include <cuda_runtime.h>
#include <cuda_bf16.h>
#include <math.h>
#include <stdint.h>

// Problem constants
#define S    64
#define NSQ  32
#define NSQC 16
#define LL   2048
#define CC   512
#define EE   128
#define HOUT_ELEMS (S*NSQ*LL)      // 4194304

typedef unsigned long long u64;
typedef unsigned int u32;

// ---------------- scratch (device globals; no allocations allowed) ----------
__device__ float         g_w[S*CC*3];                 // dyn conv weights [s][c][k]
__device__ float         g_b[S*CC];                   // dyn conv bias    [s][c]
__device__ __nv_bfloat16 g_w1h[CC*CC];                // W1 hi bf16 [o][c]
__device__ __nv_bfloat16 g_w1l[CC*CC];                // W1 lo bf16
__device__ __nv_bfloat16 g_yh[(size_t)S*LL*CC];       // 128 MB  yT hi  [s][l][c]
__device__ __nv_bfloat16 g_yl[(size_t)S*LL*CC];       // 128 MB  yT lo
__device__ __nv_bfloat16 g_w2h[3*32*CC];              // W2 hi [tap][o][c]
__device__ __nv_bfloat16 g_w2l[3*32*CC];              // W2 lo

// ---------------- mma / ldmatrix / cp.async helpers (sm_80-baseline ISA) ----
__device__ __forceinline__ u32 smem_u32(const void* p) {
    u32 a; asm("{ .reg .u64 t; cvta.to.shared.u64 t, %1; cvt.u32.u64 %0, t; }"
               : "=r"(a) : "l"(p));
    return a;
}
__device__ __forceinline__ void ldm4(u32* r, u32 addr) {
    asm volatile("ldmatrix.sync.aligned.m8n8.x4.shared.b16 {%0,%1,%2,%3}, [%4];"
                 : "=r"(r[0]), "=r"(r[1]), "=r"(r[2]), "=r"(r[3]) : "r"(addr));
}
__device__ __forceinline__ void mma16816(float* d, const u32* a, const u32* b) {
    asm volatile("mma.sync.aligned.m16n8k16.row.col.f32.bf16.bf16.f32 "
                 "{%0,%1,%2,%3}, {%4,%5,%6,%7}, {%8,%9}, {%0,%1,%2,%3};"
                 : "+f"(d[0]), "+f"(d[1]), "+f"(d[2]), "+f"(d[3])
                 : "r"(a[0]), "r"(a[1]), "r"(a[2]), "r"(a[3]), "r"(b[0]), "r"(b[1]));
}
#define CP16(sm, gp)      asm volatile("cp.async.cg.shared.global [%0], [%1], 16;" :: "r"(sm), "l"(gp))
#define CP16Z(sm, gp, sz) asm volatile("cp.async.cg.shared.global [%0], [%1], 16, %2;" :: "r"(sm), "l"(gp), "r"(sz))
#define CP_COMMIT()   asm volatile("cp.async.commit_group;" ::: "memory")
#define CP_WAIT0()    asm volatile("cp.async.wait_group 0;" ::: "memory")
#define CP_WAIT1()    asm volatile("cp.async.wait_group 1;" ::: "memory")

// gemm smem tile: 128 rows x 64 bytes, 16B chunks XOR-swizzled
__device__ __forceinline__ u32 soff(int r, int c) {
    return (u32)(r*64 + ((c ^ ((r >> 1) & 3)) * 16));
}
// bf16 hi/lo split packed into one u32 (hi = low half, lo = high half)
__device__ __forceinline__ u32 packhl(float v) {
    __nv_bfloat16 vh = __float2bfloat16_rn(v);
    float rem = v - __bfloat162float(vh);
    __nv_bfloat16 vl = __float2bfloat16_rn(rem);
    return (u32)__bfloat16_as_ushort(vh) | ((u32)__bfloat16_as_ushort(vl) << 16);
}

// ============================================================================
// Kernel A: dynamic weights (emb GEMV) + zero logdet.  grid = 64
// ============================================================================
__global__ void dynw_kernel(const float* __restrict__ emb,
                            const float* __restrict__ Wa,
                            const float* __restrict__ ba,
                            const float* __restrict__ Wb,
                            const float* __restrict__ bb,
                            float* __restrict__ logdet)
{
    int s = blockIdx.x;
    __shared__ float e[EE];
    int t = threadIdx.x;
    if (t < EE) e[t] = emb[s*EE + t];
    __syncthreads();

    for (int r = t; r < CC*3 + CC; r += blockDim.x) {
        const float* row; float bias; float* outp;
        if (r < CC*3) { row = Wa + (size_t)r*EE; bias = ba[r]; outp = &g_w[s*CC*3 + r]; }
        else { int r2 = r - CC*3; row = Wb + (size_t)r2*EE; bias = bb[r2]; outp = &g_b[s*CC + r2]; }
        float acc = bias;
        #pragma unroll 8
        for (int k = 0; k < EE; ++k) acc = fmaf(e[k], row[k], acc);
        *outp = acc;
    }
    if (t == 0) logdet[s] = 0.f;
}

// ============================================================================
// Kernel A2: W1 -> bf16 hi/lo split.  grid=512 (o), block=256
// ============================================================================
__global__ void w1cvt_kernel(const float* __restrict__ W1)
{
    int o = blockIdx.x, t = threadIdx.x;
    float2 v = *(const float2*)(W1 + (size_t)o*CC + t*2);
    u32 p0 = packhl(v.x), p1 = packhl(v.y);
    ((u32*)g_w1h)[o*256 + t] = __byte_perm(p0, p1, 0x5410);
    ((u32*)g_w1l)[o*256 + t] = __byte_perm(p0, p1, 0x7632);
}

// ============================================================================
// Kernel A3: W2[o][c][k] -> hi/lo bf16 packed [tap][o][c].  grid=192, 256 thr
// ============================================================================
__global__ void w2cvt_kernel(const float* __restrict__ W2)
{
    int idx = blockIdx.x*256 + threadIdx.x;     // < 3*32*512 = 49152
    int c   = idx & 511;
    int o   = (idx >> 9) & 31;
    int tap = idx >> 14;
    float v = W2[(size_t)o*1536 + c*3 + tap];
    __nv_bfloat16 vh = __float2bfloat16_rn(v);
    float rem = v - __bfloat162float(vh);
    g_w2h[idx] = vh;
    g_w2l[idx] = __float2bfloat16_rn(rem);
}

// ============================================================================
// Kernel C: FUSED dwconv + HMMA GEMM.  y = relu(W1 * relu(dwconv(h)) + b1)
//   The B-operand x-tile for k-chunk kt (c in [32kt,32kt+32)) depends only on
//   h1 row kt: computed in-kernel from a 544B h segment + per-sample weight
//   table (8KB smem, loaded once), written straight to the B smem buffers.
//   CTA tile 128x128, K-chunk 32, 3-stage pipeline. grid=(16 bn,4 bm,64 s).
//   Output: bf16 hi/lo transposed yT[s][l][c] (smem-staged), as before.
// ============================================================================
#define WT_OFF   0
#define STG0     8192
#define SA_H     0
#define SA_L     8192
#define SB_H     16384
#define SB_L     24576
#define SHS      32768
#define STG_STRIDE 33344                  // 32768 + 576 (544B h-seg + pad)
#define GSMEM_TOTAL (STG0 + 3*STG_STRIDE) // 108224

__global__ __launch_bounds__(256, 2)
void gemm_fused_kernel(const float* __restrict__ h, const float* __restrict__ b1)
{
    extern __shared__ __align__(128) char smem[];
    u32 sb = smem_u32(smem);
    int t = threadIdx.x, lane = t & 31, wid = t >> 5;
    int bn = blockIdx.x, bm = blockIdx.y, s = blockIdx.z;
    int wm = wid & 3;
    int wn = wid >> 2;

    // ---- weight table: WT[c] = (w0,w1,w2,b), 512 x 16B, once per CTA ----
    {
        #pragma unroll
        for (int q = 0; q < 2; ++q) {
            int c = t*2 + q;
            float4 wv = make_float4(g_w[s*CC*3 + c*3 + 0],
                                    g_w[s*CC*3 + c*3 + 1],
                                    g_w[s*CC*3 + c*3 + 2],
                                    g_b[s*CC + c]);
            *(float4*)(smem + WT_OFF + c*16) = wv;
        }
    }

    int r_ld[2], c_ld[2];
    #pragma unroll
    for (int i = 0; i < 2; ++i) { int idx = t + i*256; r_ld[i] = idx >> 2; c_ld[i] = idx & 3; }

    const uint4* w1h4 = (const uint4*)g_w1h;
    const uint4* w1l4 = (const uint4*)g_w1l;
    const float* hbase = h + (size_t)s*NSQ*LL;     // h1 row kt = hbase + kt*LL

    auto load_buf = [&](int buf, int kt) {
        u32 st = sb + STG0 + buf*STG_STRIDE;
        int k0 = kt*32;
        #pragma unroll
        for (int i = 0; i < 2; ++i) {
            int r = r_ld[i], c = c_ld[i];
            u32 so = soff(r, c);
            size_t ka = (size_t)(bm*128 + r)*CC + k0 + c*8;
            CP16(st + SA_H + so, w1h4 + (ka >> 3));
            CP16(st + SA_L + so, w1l4 + (ka >> 3));
        }
        if (t < 34) {
            int g = bn*128 - 4 + t*4;
            bool ok = (g >= 0) && (g < LL);
            const float* src = hbase + (size_t)kt*LL + (ok ? g : 0);
            CP16Z(st + SHS + t*16, src, ok ? 16u : 0u);
        }
    };

    // in-kernel dwconv: x[r][c2*2 .. +1] for this stage's 32 channels
    auto xcomp = [&](int buf, int kt) {
        char* st = smem + STG0 + buf*STG_STRIDE;
        int c2 = t & 15, lg = t >> 4;
        float4 wv0 = *(const float4*)(smem + WT_OFF + (kt*32 + c2*2)*16);
        float4 wv1 = *(const float4*)(smem + WT_OFF + (kt*32 + c2*2 + 1)*16);
        const float* hs = (const float*)(st + SHS);
        float hv[10];
        #pragma unroll
        for (int j = 0; j < 10; ++j) hv[j] = hs[lg*8 + 3 + j];
        #pragma unroll
        for (int j = 0; j < 8; ++j) {
            int r = lg*8 + j;
            float v0 = fmaf(wv0.x, hv[j], fmaf(wv0.y, hv[j+1], fmaf(wv0.z, hv[j+2], wv0.w)));
            float v1 = fmaf(wv1.x, hv[j], fmaf(wv1.y, hv[j+1], fmaf(wv1.z, hv[j+2], wv1.w)));
            u32 p0 = packhl(fmaxf(v0, 0.f));
            u32 p1 = packhl(fmaxf(v1, 0.f));
            u32 off = (u32)(r*64 + (((c2 >> 2) ^ ((r >> 1) & 3))*16) + (c2 & 3)*4);
            *(u32*)(st + SB_H + off) = __byte_perm(p0, p1, 0x5410);
            *(u32*)(st + SB_L + off) = __byte_perm(p0, p1, 0x7632);
        }
    };

    float acc[2][8][4];
    #pragma unroll
    for (int i = 0; i < 2; ++i)
        #pragma unroll
        for (int j = 0; j < 8; ++j)
            #pragma unroll
            for (int q = 0; q < 4; ++q) acc[i][j][q] = 0.f;

    load_buf(0, 0); CP_COMMIT();
    load_buf(1, 1); CP_COMMIT();

    int buf = 0;
    for (int kt = 0; kt < 16; ++kt) {
        CP_WAIT1();
        __syncthreads();
        if (kt < 14) {
            int nb = buf + 2; if (nb >= 3) nb -= 3;
            load_buf(nb, kt + 2);
            CP_COMMIT();
        }
        xcomp(buf, kt);
        __syncthreads();

        u32 base = sb + STG0 + buf*STG_STRIDE;
        #pragma unroll
        for (int ks = 0; ks < 2; ++ks) {
            u32 a_h[2][4], a_l[2][4];
            #pragma unroll
            for (int ti = 0; ti < 2; ++ti) {
                int row = wm*32 + ti*16 + (lane & 15);
                int ch  = ks*2 + (lane >> 4);
                u32 so = soff(row, ch);
                ldm4(a_h[ti], base + SA_H + so);
                ldm4(a_l[ti], base + SA_L + so);
            }
            u32 b_h[8][2], b_l[8][2];
            #pragma unroll
            for (int g = 0; g < 4; ++g) {
                int row = wn*64 + g*16 + (lane & 7) + 8*(lane >> 4);
                int ch  = ks*2 + ((lane >> 3) & 1);
                u32 so = soff(row, ch);
                u32 rh[4], rl[4];
                ldm4(rh, base + SB_H + so);
                ldm4(rl, base + SB_L + so);
                b_h[2*g][0] = rh[0]; b_h[2*g][1] = rh[1];
                b_h[2*g+1][0] = rh[2]; b_h[2*g+1][1] = rh[3];
                b_l[2*g][0] = rl[0]; b_l[2*g][1] = rl[1];
                b_l[2*g+1][0] = rl[2]; b_l[2*g+1][1] = rl[3];
            }
            #pragma unroll
            for (int i = 0; i < 2; ++i)
                #pragma unroll
                for (int j = 0; j < 8; ++j) {
                    mma16816(acc[i][j], a_h[i], b_h[j]);
                    mma16816(acc[i][j], a_h[i], b_l[j]);
                    mma16816(acc[i][j], a_l[i], b_h[j]);
                }
        }
        if (++buf == 3) buf = 0;
    }

    // ---- epilogue: relu(+bias) -> packed (hi|lo<<16) u32, smem transpose ----
    __syncthreads();
    u32* ysm2 = (u32*)smem;                     // [l 128][stride 132]
    #pragma unroll
    for (int i = 0; i < 2; ++i) {
        int rA = wm*32 + i*16 + (lane >> 2);
        int rB = rA + 8;
        float bA = b1[bm*128 + rA], bB = b1[bm*128 + rB];
        #pragma unroll
        for (int j = 0; j < 8; ++j) {
            int lc = wn*64 + j*8 + 2*(lane & 3);
            float* d = acc[i][j];
            ysm2[lc*132 + rA]       = packhl(fmaxf(d[0] + bA, 0.f));
            ysm2[(lc+1)*132 + rA]   = packhl(fmaxf(d[1] + bA, 0.f));
            ysm2[lc*132 + rB]       = packhl(fmaxf(d[2] + bB, 0.f));
            ysm2[(lc+1)*132 + rB]   = packhl(fmaxf(d[3] + bB, 0.f));
        }
    }
    __syncthreads();
    {
        int lr = t >> 1, half = t & 1;
        size_t gbase = ((size_t)s*LL + bn*128 + lr)*CC + bm*128 + half*64;
        const u32* src = ysm2 + lr*132 + half*64;
        #pragma unroll
        for (int q = 0; q < 8; ++q) {
            uint4 w0 = *(const uint4*)(src + q*8);
            uint4 w1 = *(const uint4*)(src + q*8 + 4);
            uint4 vh = make_uint4(__byte_perm(w0.x, w0.y, 0x5410),
                                  __byte_perm(w0.z, w0.w, 0x5410),
                                  __byte_perm(w1.x, w1.y, 0x5410),
                                  __byte_perm(w1.z, w1.w, 0x5410));
            uint4 vl = make_uint4(__byte_perm(w0.x, w0.y, 0x7632),
                                  __byte_perm(w0.z, w0.w, 0x7632),
                                  __byte_perm(w1.x, w1.y, 0x7632),
                                  __byte_perm(w1.z, w1.w, 0x7632));
            *(uint4*)(g_yh + gbase + q*8) = vh;
            *(uint4*)(g_yl + gbase + q*8) = vl;
        }
    }
}

// ============================================================================
// Kernel D: conv2 via HMMA.  out[o][l] = sum_{c,k} W2[o][c][k] y[c][l+k-1]
//   M=32, N=128 per CTA (2 CTAs/SM), K = 512 c x 3 taps, c-chunks of 32,
//   double-buffered cp.async. 8 warps, warp tile 32m x 16n.
//   Fused sigmoid/coupling/logdet/h1-copy.  grid=(16 ltile, 64 s), 256 thr
// ============================================================================
#define C2_BT   10400          // B tile: 130 rows x 80B
#define C2_AT   7680           // A tile: 96 rows x 80B
#define C2_STAGE (2*C2_BT + 2*C2_AT)       // 36160
#define C2_BB(b) ((b)*C2_STAGE)            // Bh; Bl = +C2_BT
#define C2_AB(b) ((b)*C2_STAGE + 2*C2_BT)  // Ah; Al = +C2_AT
#define C2_SMEM  (2*C2_STAGE)              // 72320

__global__ __launch_bounds__(256, 2)
void conv2_mma_kernel(const float* __restrict__ h,
                      const float* __restrict__ b2,
                      float* __restrict__ out)
{
    extern __shared__ __align__(128) char smem[];
    u32 sb = smem_u32(smem);
    int t = threadIdx.x, lane = t & 31, wid = t >> 5;
    int lt = blockIdx.x, s = blockIdx.y;
    int l0 = lt * 128;

    const __nv_bfloat16* Yh = g_yh + (size_t)s*LL*CC;
    const __nv_bfloat16* Yl = g_yl + (size_t)s*LL*CC;

    auto load_cc = [&](int buf, int cc) {
        u32 bB = sb + C2_BB(buf);
        for (int idx = t; idx < 520; idx += 256) {        // 130 rows x 4 chunks
            int r = idx >> 2, ch = idx & 3;
            int l = l0 - 1 + r;
            bool ok = ((unsigned)l < (unsigned)LL);
            u32 sz = ok ? 16u : 0u;
            size_t goff = (size_t)(ok ? l : 0)*CC + cc*32 + ch*8;
            u32 dst = bB + r*80 + ch*16;
            CP16Z(dst,         Yh + goff, sz);
            CP16Z(dst + C2_BT, Yl + goff, sz);
        }
        u32 bA = sb + C2_AB(buf);
        for (int idx = t; idx < 384; idx += 256) {        // 96 rows x 4 chunks
            int r = idx >> 2, ch = idx & 3;
            size_t goff = (size_t)r*CC + cc*32 + ch*8;
            u32 dst = bA + r*80 + ch*16;
            CP16(dst,         g_w2h + goff);
            CP16(dst + C2_AT, g_w2l + goff);
        }
    };

    float acc[2][2][4];
    #pragma unroll
    for (int i = 0; i < 2; ++i)
        #pragma unroll
        for (int j = 0; j < 2; ++j)
            #pragma unroll
            for (int q = 0; q < 4; ++q) acc[i][j][q] = 0.f;

    load_cc(0, 0); CP_COMMIT();

    int buf = 0;
    for (int cc = 0; cc < 16; ++cc) {
        CP_WAIT0();
        __syncthreads();
        if (cc < 15) { load_cc(buf ^ 1, cc + 1); CP_COMMIT(); }

        u32 bB = sb + C2_BB(buf);
        u32 bA = sb + C2_AB(buf);
        #pragma unroll
        for (int tap = 0; tap < 3; ++tap) {
            #pragma unroll
            for (int ks = 0; ks < 2; ++ks) {
                u32 a_h[2][4], a_l[2][4];
                #pragma unroll
                for (int ti = 0; ti < 2; ++ti) {
                    int row = tap*32 + ti*16 + (lane & 15);
                    int ch  = ks*2 + (lane >> 4);
                    u32 ad = bA + row*80 + ch*16;
                    ldm4(a_h[ti], ad);
                    ldm4(a_l[ti], ad + C2_AT);
                }
                u32 b_h[2][2], b_l[2][2];
                {
                    int row = wid*16 + (lane & 7) + 8*(lane >> 4) + tap;
                    int ch  = ks*2 + ((lane >> 3) & 1);
                    u32 ad = bB + row*80 + ch*16;
                    u32 rh[4], rl[4];
                    ldm4(rh, ad);
                    ldm4(rl, ad + C2_BT);
                    b_h[0][0] = rh[0]; b_h[0][1] = rh[1];
                    b_h[1][0] = rh[2]; b_h[1][1] = rh[3];
                    b_l[0][0] = rl[0]; b_l[0][1] = rl[1];
                    b_l[1][0] = rl[2]; b_l[1][1] = rl[3];
                }
                #pragma unroll
                for (int i = 0; i < 2; ++i)
                    #pragma unroll
                    for (int j = 0; j < 2; ++j) {
                        mma16816(acc[i][j], a_h[i], b_h[j]);
                        mma16816(acc[i][j], a_h[i], b_l[j]);
                        mma16816(acc[i][j], a_l[i], b_h[j]);
                    }
            }
        }
        buf ^= 1;
    }

    // ---- fused epilogue: i=0 frags are s-channels (o 0..15), i=1 are m ----
    int o2a = lane >> 2, o2b = o2a + 8;
    float bsA = b2[o2a],      bsB = b2[o2b];
    float bmA = b2[16 + o2a], bmB = b2[16 + o2b];
    const float* h2A = h + ((size_t)s*NSQ + 16 + o2a)*LL;
    const float* h2B = h + ((size_t)s*NSQ + 16 + o2b)*LL;
    float* oA = out + ((size_t)s*NSQ + 16 + o2a)*LL;
    float* oB = out + ((size_t)s*NSQ + 16 + o2b)*LL;

    float logsum = 0.f;
    #pragma unroll
    for (int j = 0; j < 2; ++j) {
        int l = l0 + wid*16 + j*8 + 2*(lane & 3);
        float2 hA = *(const float2*)(h2A + l);
        float2 hB = *(const float2*)(h2B + l);
        float sg0 = 1.f/(1.f + expf(-(acc[0][j][0] + bsA + 2.f))) + 1e-7f;
        float sg1 = 1.f/(1.f + expf(-(acc[0][j][1] + bsA + 2.f))) + 1e-7f;
        float sg2 = 1.f/(1.f + expf(-(acc[0][j][2] + bsB + 2.f))) + 1e-7f;
        float sg3 = 1.f/(1.f + expf(-(acc[0][j][3] + bsB + 2.f))) + 1e-7f;
        float2 rA = make_float2(sg0*(hA.x + acc[1][j][0] + bmA),
                                sg1*(hA.y + acc[1][j][1] + bmA));
        float2 rB = make_float2(sg2*(hB.x + acc[1][j][2] + bmB),
                                sg3*(hB.y + acc[1][j][3] + bmB));
        *(float2*)(oA + l) = rA;
        *(float2*)(oB + l) = rB;
        logsum += logf(sg0) + logf(sg1) + logf(sg2) + logf(sg3);
    }
    #pragma unroll
    for (int off = 16; off; off >>= 1)
        logsum += __shfl_xor_sync(0xffffffffu, logsum, off);
    if (lane == 0)
        atomicAdd(out + HOUT_ELEMS + s, logsum);

    // h1 passthrough for this l-tile
    for (int idx = t; idx < NSQC*128; idx += 256) {
        int ch = idx >> 7;
        int l  = l0 + (idx & 127);
        size_t off = ((size_t)s*NSQ + ch)*LL + l;
        out[off] = h[off];
    }
}

// ============================================================================
extern "C" void kernel_launch(void* const* d_in, const int* in_sizes, int n_in,
                              void* d_out, int out_size)
{
    const float* h   = (const float*)d_in[0];
    const float* emb = (const float*)d_in[1];
    const float* Wa  = (const float*)d_in[2];
    const float* ba  = (const float*)d_in[3];
    const float* Wb  = (const float*)d_in[4];
    const float* bb  = (const float*)d_in[5];
    const float* W1  = (const float*)d_in[6];
    const float* b1  = (const float*)d_in[7];
    const float* W2  = (const float*)d_in[8];
    const float* b2  = (const float*)d_in[9];
    float* out = (float*)d_out;

    static bool attr_set = false;
    if (!attr_set) {
        cudaFuncSetAttribute(gemm_fused_kernel,
                             cudaFuncAttributeMaxDynamicSharedMemorySize, GSMEM_TOTAL);
        cudaFuncSetAttribute(conv2_mma_kernel,
                             cudaFuncAttributeMaxDynamicSharedMemorySize, C2_SMEM);
        attr_set = true;
    }

    dynw_kernel<<<S, 256>>>(emb, Wa, ba, Wb, bb, out + HOUT_ELEMS);
    w1cvt_kernel<<<CC, 256>>>(W1);
    w2cvt_kernel<<<192, 256>>>(W2);
    gemm_fused_kernel<<<dim3(16, 4, S), 256, GSMEM_TOTAL>>>(h, b1);
    conv2_mma_kernel<<<dim3(16, S), 256, C2_SMEM>>>(h, b2, out);
}